// round 2
// baseline (speedup 1.0000x reference)
#include <cuda_runtime.h>
#include <cuda_bf16.h>
#include <cstdint>

#define EPS   1e-5f
#define NB    512
#define NP    512
#define M_TOT (NB*NP)

// ---------------- scratch ----------------------------------------------------
__device__ float g_h [(size_t)M_TOT * 128];
__device__ float g_y [(size_t)M_TOT * 256];
__device__ float g_h2[(size_t)M_TOT * 256];
__device__ float g_pooled[NB * 256];
__device__ float g_pb    [NB * 256];
__device__ float g_sum1[128], g_ss1[128];
__device__ float g_sum2[256], g_ss2[256];
__device__ float g_cnt;
__device__ float g_scale1[128], g_shift1[128];
__device__ float g_scale2[256], g_shift2[256];

// ---------------- init -------------------------------------------------------
__global__ void k_init(float* __restrict__ out, float* __restrict__ pooled) {
    int i = blockIdx.x * blockDim.x + threadIdx.x;
    if (i < 65536)  out[i] = 0.f;
    if (i < 131072) pooled[i] = 0.f;
    if (i < 128) { g_sum1[i] = 0.f; g_ss1[i] = 0.f; }
    if (i < 256) { g_sum2[i] = 0.f; g_ss2[i] = 0.f; }
    if (i == 0)  g_cnt = 0.f;
}

// ---------------- K1: h = x@W1+b1 + masked stats ------------------------------
__global__ void k_h_stats(const float* __restrict__ x, const int* __restrict__ mask,
                          const float* __restrict__ W1, const float* __restrict__ b1) {
    int c  = threadIdx.x;
    int p0 = blockIdx.x * 128;
    __shared__ float xs[128 * 6];
    __shared__ int   ms[128];
    for (int idx = c; idx < 768; idx += 128) xs[idx] = x[p0 * 6 + idx];
    ms[c] = mask[p0 + c];
    __syncthreads();
    float w0 = W1[0*128+c], w1 = W1[1*128+c], w2 = W1[2*128+c];
    float w3 = W1[3*128+c], w4 = W1[4*128+c], w5 = W1[5*128+c];
    float bb = b1[c];
    float s = 0.f, ss = 0.f; int cnt = 0;
    for (int i = 0; i < 128; i++) {
        const float* xp = &xs[i * 6];
        float t = bb + xp[0]*w0 + xp[1]*w1 + xp[2]*w2 + xp[3]*w3 + xp[4]*w4 + xp[5]*w5;
        g_h[(size_t)(p0 + i) * 128 + c] = t;
        if (ms[i]) { s += t; ss += t * t; cnt++; }
    }
    atomicAdd(&g_sum1[c], s);
    atomicAdd(&g_ss1[c],  ss);
    if (c == 0) atomicAdd(&g_cnt, (float)cnt);
}

// ---------------- BN finalize -------------------------------------------------
__global__ void k_fin1(const float* __restrict__ g1, const float* __restrict__ be1) {
    int c = threadIdx.x;
    float cnt  = g_cnt;
    float mean = g_sum1[c] / cnt;
    float var  = g_ss1[c] / cnt - mean * mean;
    float sc   = g1[c] * rsqrtf(var + EPS);
    g_scale1[c] = sc;
    g_shift1[c] = be1[c] - mean * sc;
}
__global__ void k_fin2(const float* __restrict__ g2, const float* __restrict__ be2) {
    int c = threadIdx.x;
    float cnt  = g_cnt;
    float mean = g_sum2[c] / cnt;
    float var  = g_ss2[c] / cnt - mean * mean;
    float sc   = g2[c] * rsqrtf(var + EPS);
    g_scale2[c] = sc;
    g_shift2[c] = be2[c] - mean * sc;
}

// ---------------- bf16 split helpers ------------------------------------------
__device__ __forceinline__ void split_bf16(float v, __nv_bfloat16& hi, __nv_bfloat16& lo) {
    hi = __float2bfloat16(v);
    lo = __float2bfloat16(v - __bfloat162float(hi));
}
__device__ __forceinline__ void mma_bf16(float* c, const uint32_t* a, uint32_t b0, uint32_t b1) {
    asm volatile(
        "mma.sync.aligned.m16n8k16.row.col.f32.bf16.bf16.f32 "
        "{%0,%1,%2,%3},{%4,%5,%6,%7},{%8,%9},{%0,%1,%2,%3};\n"
        : "+f"(c[0]), "+f"(c[1]), "+f"(c[2]), "+f"(c[3])
        : "r"(a[0]), "r"(a[1]), "r"(a[2]), "r"(a[3]), "r"(b0), "r"(b1));
}

// ---------------- tensor GEMM: 128x128 tile, BK=32, 256 thr, bf16-split -------
// AMODE: 1 = relu(A*scale[k]+shift[k]) on load
// EMODE: 0 = (+bias[col])*mask[row] store + fused max-pool into g_pooled
//        1 = +biasB[batch*256+col] store raw + fused masked stats -> g_sum2/g_ss2
//        2 = (+bias[col])*mask[row], block max, atomicMax -> C[batch*NTOT+col]
template<int KTOT, int NTOT, int AMODE, int EMODE>
__global__ void __launch_bounds__(256) k_tgemm(
    const float* __restrict__ A, const float* __restrict__ Bm,
    const float* __restrict__ bias, const int* __restrict__ mask,
    const float* __restrict__ scA, const float* __restrict__ shA,
    float* __restrict__ C, float* __restrict__ pooled)
{
    __shared__ __nv_bfloat16 Ah[128][40], Al[128][40];   // [m][k]
    __shared__ __nv_bfloat16 Bh[128][40], Bl[128][40];   // [n][k] (transposed)

    const int tid  = threadIdx.x;
    const int lane = tid & 31, wid = tid >> 5;
    const int warp_m = wid & 3, warp_n = wid >> 2;
    const int g = lane >> 2, t4 = lane & 3;
    const int rowBase = blockIdx.y * 128;
    const int colBase = blockIdx.x * 128;

    // loader mapping
    const int aRow = tid >> 1;                 // 0..127
    const int aKq  = (tid & 1) * 16;           // 0 | 16
    const int bK   = tid >> 3;                 // 0..31
    const int bN   = (tid & 7) * 16;           // 0..112

    float acc[2][8][4];
#pragma unroll
    for (int i = 0; i < 2; i++)
#pragma unroll
        for (int j = 0; j < 8; j++)
#pragma unroll
            for (int l = 0; l < 4; l++) acc[i][j][l] = 0.f;

    const float* Ap = A + (size_t)(rowBase + aRow) * KTOT + aKq;

    for (int k0 = 0; k0 < KTOT; k0 += 32) {
        // --- A tile (with optional BN+ReLU), split to hi/lo ---
#pragma unroll
        for (int j = 0; j < 4; j++) {
            float4 v = *(const float4*)(Ap + k0 + j * 4);
            if (AMODE == 1) {
                float4 s = *(const float4*)&scA[k0 + aKq + j * 4];
                float4 h = *(const float4*)&shA[k0 + aKq + j * 4];
                v.x = fmaxf(v.x * s.x + h.x, 0.f);
                v.y = fmaxf(v.y * s.y + h.y, 0.f);
                v.z = fmaxf(v.z * s.z + h.z, 0.f);
                v.w = fmaxf(v.w * s.w + h.w, 0.f);
            }
            int kk = aKq + j * 4;
            split_bf16(v.x, Ah[aRow][kk+0], Al[aRow][kk+0]);
            split_bf16(v.y, Ah[aRow][kk+1], Al[aRow][kk+1]);
            split_bf16(v.z, Ah[aRow][kk+2], Al[aRow][kk+2]);
            split_bf16(v.w, Ah[aRow][kk+3], Al[aRow][kk+3]);
        }
        // --- B tile, transpose into [n][k], split ---
#pragma unroll
        for (int j = 0; j < 4; j++) {
            float4 v = *(const float4*)&Bm[(size_t)(k0 + bK) * NTOT + colBase + bN + j * 4];
            int n = bN + j * 4;
            split_bf16(v.x, Bh[n+0][bK], Bl[n+0][bK]);
            split_bf16(v.y, Bh[n+1][bK], Bl[n+1][bK]);
            split_bf16(v.z, Bh[n+2][bK], Bl[n+2][bK]);
            split_bf16(v.w, Bh[n+3][bK], Bl[n+3][bK]);
        }
        __syncthreads();

#pragma unroll
        for (int kk = 0; kk < 2; kk++) {
            const int ko = kk * 16 + 2 * t4;
            uint32_t ah[2][4], al[2][4];
#pragma unroll
            for (int mt = 0; mt < 2; mt++) {
                int ar = warp_m * 32 + mt * 16;
                ah[mt][0] = *(const uint32_t*)&Ah[ar + g    ][ko];
                ah[mt][1] = *(const uint32_t*)&Ah[ar + g + 8][ko];
                ah[mt][2] = *(const uint32_t*)&Ah[ar + g    ][ko + 8];
                ah[mt][3] = *(const uint32_t*)&Ah[ar + g + 8][ko + 8];
                al[mt][0] = *(const uint32_t*)&Al[ar + g    ][ko];
                al[mt][1] = *(const uint32_t*)&Al[ar + g + 8][ko];
                al[mt][2] = *(const uint32_t*)&Al[ar + g    ][ko + 8];
                al[mt][3] = *(const uint32_t*)&Al[ar + g + 8][ko + 8];
            }
#pragma unroll
            for (int nt = 0; nt < 8; nt++) {
                int bn = warp_n * 64 + nt * 8 + g;
                uint32_t bh0 = *(const uint32_t*)&Bh[bn][ko];
                uint32_t bh1 = *(const uint32_t*)&Bh[bn][ko + 8];
                uint32_t bl0 = *(const uint32_t*)&Bl[bn][ko];
                uint32_t bl1 = *(const uint32_t*)&Bl[bn][ko + 8];
#pragma unroll
                for (int mt = 0; mt < 2; mt++) {
                    mma_bf16(acc[mt][nt], ah[mt], bh0, bh1);
                    mma_bf16(acc[mt][nt], ah[mt], bl0, bl1);
                    mma_bf16(acc[mt][nt], al[mt], bh0, bh1);
                }
            }
        }
        __syncthreads();
    }

    const int batch = rowBase >> 9;

    if (EMODE == 0) {
        // store masked y, fused max-pool
        int* pool = (int*)&Ah[0][0];
        if (tid < 128) pool[tid] = 0;
        __syncthreads();
#pragma unroll
        for (int mt = 0; mt < 2; mt++) {
            int r0 = rowBase + warp_m * 32 + mt * 16 + g;
            int r1 = r0 + 8;
            float m0 = (mask[r0] != 0) ? 1.f : 0.f;
            float m1 = (mask[r1] != 0) ? 1.f : 0.f;
#pragma unroll
            for (int nt = 0; nt < 8; nt++) {
                int c0 = colBase + warp_n * 64 + nt * 8 + 2 * t4;
                float bx = bias[c0], by = bias[c0 + 1];
                float v00 = (acc[mt][nt][0] + bx) * m0;
                float v01 = (acc[mt][nt][1] + by) * m0;
                float v10 = (acc[mt][nt][2] + bx) * m1;
                float v11 = (acc[mt][nt][3] + by) * m1;
                *(float2*)&C[(size_t)r0 * NTOT + c0] = make_float2(v00, v01);
                *(float2*)&C[(size_t)r1 * NTOT + c0] = make_float2(v10, v11);
                int lc = warp_n * 64 + nt * 8 + 2 * t4;
                float p0 = fmaxf(v00, v10), p1 = fmaxf(v01, v11);
                if (p0 > 0.f) atomicMax(&pool[lc],     __float_as_int(p0));
                if (p1 > 0.f) atomicMax(&pool[lc + 1], __float_as_int(p1));
            }
        }
        __syncthreads();
        if (tid < 128) {
            int v = pool[tid];
            if (v > 0) atomicMax((int*)&pooled[batch * 256 + colBase + tid], v);
        }
    } else if (EMODE == 1) {
        // store raw h2 (+per-batch bias), fused masked stats
        float* sArr  = (float*)&Ah[0][0];
        float* ssArr = (float*)&Bh[0][0];
        if (tid < 128) { sArr[tid] = 0.f; ssArr[tid] = 0.f; }
        __syncthreads();
#pragma unroll
        for (int nt = 0; nt < 8; nt++) {
            int c0 = colBase + warp_n * 64 + nt * 8 + 2 * t4;
            float bx = bias[batch * 256 + c0], by = bias[batch * 256 + c0 + 1];
            float s0 = 0.f, s1 = 0.f, q0 = 0.f, q1 = 0.f;
#pragma unroll
            for (int mt = 0; mt < 2; mt++) {
                int r0 = rowBase + warp_m * 32 + mt * 16 + g;
                int r1 = r0 + 8;
                float v00 = acc[mt][nt][0] + bx;
                float v01 = acc[mt][nt][1] + by;
                float v10 = acc[mt][nt][2] + bx;
                float v11 = acc[mt][nt][3] + by;
                *(float2*)&C[(size_t)r0 * NTOT + c0] = make_float2(v00, v01);
                *(float2*)&C[(size_t)r1 * NTOT + c0] = make_float2(v10, v11);
                if (mask[r0]) { s0 += v00; s1 += v01; q0 += v00*v00; q1 += v01*v01; }
                if (mask[r1]) { s0 += v10; s1 += v11; q0 += v10*v10; q1 += v11*v11; }
            }
            int lc = warp_n * 64 + nt * 8 + 2 * t4;
            atomicAdd(&sArr[lc],      s0);
            atomicAdd(&sArr[lc + 1],  s1);
            atomicAdd(&ssArr[lc],     q0);
            atomicAdd(&ssArr[lc + 1], q1);
        }
        __syncthreads();
        if (tid < 128) {
            atomicAdd(&g_sum2[colBase + tid], sArr[tid]);
            atomicAdd(&g_ss2[colBase + tid],  ssArr[tid]);
        }
    } else {
        // masked max -> out
        int* pool = (int*)&Ah[0][0];
        if (tid < 128) pool[tid] = 0;
        __syncthreads();
#pragma unroll
        for (int nt = 0; nt < 8; nt++) {
            int c0 = colBase + warp_n * 64 + nt * 8 + 2 * t4;
            float bx = bias[c0], by = bias[c0 + 1];
            float p0 = 0.f, p1 = 0.f;
#pragma unroll
            for (int mt = 0; mt < 2; mt++) {
                int r0 = rowBase + warp_m * 32 + mt * 16 + g;
                int r1 = r0 + 8;
                float m0 = (mask[r0] != 0) ? 1.f : 0.f;
                float m1 = (mask[r1] != 0) ? 1.f : 0.f;
                p0 = fmaxf(p0, (acc[mt][nt][0] + bx) * m0);
                p1 = fmaxf(p1, (acc[mt][nt][1] + by) * m0);
                p0 = fmaxf(p0, (acc[mt][nt][2] + bx) * m1);
                p1 = fmaxf(p1, (acc[mt][nt][3] + by) * m1);
            }
            int lc = warp_n * 64 + nt * 8 + 2 * t4;
            if (p0 > 0.f) atomicMax(&pool[lc],     __float_as_int(p0));
            if (p1 > 0.f) atomicMax(&pool[lc + 1], __float_as_int(p1));
        }
        __syncthreads();
        if (tid < 128) {
            int v = pool[tid];
            if (v > 0) atomicMax((int*)&C[batch * NTOT + colBase + tid], v);
        }
    }
}

// ---------------- pb[b,j] = b3[j] + pooled[b,:] @ W3[256:,:] -------------------
__global__ void k_pb(const float* __restrict__ W3, const float* __restrict__ b3) {
    int b = blockIdx.x, j = threadIdx.x;
    __shared__ float pl[256];
    pl[j] = g_pooled[b * 256 + j];
    __syncthreads();
    float s = b3[j];
#pragma unroll 4
    for (int k = 0; k < 256; k++) s += pl[k] * W3[(256 + k) * 256 + j];
    g_pb[b * 256 + j] = s;
}

// ---------------- launch --------------------------------------------------------
extern "C" void kernel_launch(void* const* d_in, const int* in_sizes, int n_in,
                              void* d_out, int out_size) {
    const float* x   = (const float*)d_in[0];
    const int*   mask= (const int*)  d_in[1];
    const float* W1  = (const float*)d_in[2];
    const float* b1  = (const float*)d_in[3];
    const float* g1  = (const float*)d_in[4];
    const float* be1 = (const float*)d_in[5];
    const float* W2  = (const float*)d_in[6];
    const float* b2  = (const float*)d_in[7];
    const float* W3  = (const float*)d_in[8];
    const float* b3  = (const float*)d_in[9];
    const float* g2  = (const float*)d_in[10];
    const float* be2 = (const float*)d_in[11];
    const float* W4  = (const float*)d_in[12];
    const float* b4  = (const float*)d_in[13];
    float* out = (float*)d_out;

    float *p_h, *p_y, *p_h2, *p_pb, *p_pooled, *p_sc1, *p_sh1, *p_sc2, *p_sh2;
    cudaGetSymbolAddress((void**)&p_h,     g_h);
    cudaGetSymbolAddress((void**)&p_y,     g_y);
    cudaGetSymbolAddress((void**)&p_h2,    g_h2);
    cudaGetSymbolAddress((void**)&p_pb,    g_pb);
    cudaGetSymbolAddress((void**)&p_pooled,g_pooled);
    cudaGetSymbolAddress((void**)&p_sc1,   g_scale1);
    cudaGetSymbolAddress((void**)&p_sh1,   g_shift1);
    cudaGetSymbolAddress((void**)&p_sc2,   g_scale2);
    cudaGetSymbolAddress((void**)&p_sh2,   g_shift2);

    k_init   <<<512, 256>>>(out, p_pooled);
    k_h_stats<<<2048, 128>>>(x, mask, W1, b1);
    k_fin1   <<<1, 128>>>(g1, be1);
    // GEMM2: y = (relu(bn1(g_h)) @ W2 + b2) * mask   (+ fused max-pool)
    k_tgemm<128, 256, 1, 0><<<dim3(2, 2048), 256>>>(p_h, W2, b2, mask, p_sc1, p_sh1, p_y, p_pooled);
    k_pb     <<<512, 256>>>(W3, b3);
    // GEMM3: h2 = y @ W3[:256,:] + pb[batch]          (+ fused BN2 stats)
    k_tgemm<256, 256, 0, 1><<<dim3(2, 2048), 256>>>(p_y, W3, p_pb, mask, nullptr, nullptr, p_h2, nullptr);
    k_fin2   <<<1, 256>>>(g2, be2);
    // GEMM4: out = max_n ((relu(bn2(h2)) @ W4 + b4) * mask)
    k_tgemm<256, 128, 1, 2><<<dim3(1, 2048), 256>>>(p_h2, W4, b4, mask, p_sc2, p_sh2, out, nullptr);
}

// round 4
// speedup vs baseline: 1.8475x; 1.8475x over previous
#include <cuda_runtime.h>
#include <cuda_bf16.h>
#include <cstdint>

#define EPS 1e-5f
#define NB  512
#define NP  512
#define MT  (NB*NP)

// ---------------- device scratch ----------------
__device__ float g_h [(size_t)MT * 128];
__device__ float g_h2[(size_t)MT * 256];
__device__ __nv_bfloat16 g_yhi[(size_t)MT * 256];
__device__ __nv_bfloat16 g_ylo[(size_t)MT * 256];
__device__ __nv_bfloat16 g_w2hi[256*128], g_w2lo[256*128];
__device__ __nv_bfloat16 g_w3hi[256*256], g_w3lo[256*256];
__device__ __nv_bfloat16 g_w4hi[128*256], g_w4lo[128*256];
__device__ float g_pooled[NB*256];
__device__ float g_pb[NB*256];
__device__ float g_sum1[128], g_ss1[128];
__device__ float g_sum2[256], g_ss2[256];
__device__ float g_cnt;
__device__ float g_scale1[128], g_shift1[128];
__device__ float g_scale2[256], g_shift2[256];

// ---------------- helpers ----------------
__device__ __forceinline__ uint32_t smem_u32(const void* p) {
    uint32_t a;
    asm("{ .reg .u64 t; cvta.to.shared.u64 t, %1; cvt.u32.u64 %0, t; }" : "=r"(a) : "l"(p));
    return a;
}
__device__ __forceinline__ void ldsm4(uint32_t* r, uint32_t addr) {
    asm volatile("ldmatrix.sync.aligned.m8n8.x4.shared.b16 {%0,%1,%2,%3}, [%4];"
        : "=r"(r[0]), "=r"(r[1]), "=r"(r[2]), "=r"(r[3]) : "r"(addr));
}
__device__ __forceinline__ void mma_bf16(float* c, const uint32_t* a, uint32_t b0, uint32_t b1) {
    asm volatile(
        "mma.sync.aligned.m16n8k16.row.col.f32.bf16.bf16.f32 "
        "{%0,%1,%2,%3},{%4,%5,%6,%7},{%8,%9},{%0,%1,%2,%3};\n"
        : "+f"(c[0]), "+f"(c[1]), "+f"(c[2]), "+f"(c[3])
        : "r"(a[0]), "r"(a[1]), "r"(a[2]), "r"(a[3]), "r"(b0), "r"(b1));
}
__device__ __forceinline__ uint32_t pk(float a, float b) {
    __nv_bfloat162 t;
    t.x = __float2bfloat16(a); t.y = __float2bfloat16(b);
    return *(uint32_t*)&t;
}

// ---------------- small kernels ----------------
__global__ void k_init(float* __restrict__ out, float* __restrict__ pooled) {
    int i = blockIdx.x * blockDim.x + threadIdx.x;
    if (i < 65536)  out[i] = 0.f;
    if (i < 131072) pooled[i] = 0.f;
    if (i < 128) { g_sum1[i] = 0.f; g_ss1[i] = 0.f; }
    if (i < 256) { g_sum2[i] = 0.f; g_ss2[i] = 0.f; }
    if (i == 0)  g_cnt = 0.f;
}

template<int K, int N>
__global__ void k_wprep(const float* __restrict__ W,
                        __nv_bfloat16* __restrict__ Whi, __nv_bfloat16* __restrict__ Wlo) {
    int n = blockIdx.x;
    for (int k = threadIdx.x; k < K; k += blockDim.x) {
        float v = W[(size_t)k * N + n];
        __nv_bfloat16 h = __float2bfloat16(v);
        Whi[(size_t)n * K + k] = h;
        Wlo[(size_t)n * K + k] = __float2bfloat16(v - __bfloat162float(h));
    }
}

__global__ void k_h_stats(const float* __restrict__ x, const int* __restrict__ mask,
                          const float* __restrict__ W1, const float* __restrict__ b1) {
    int c  = threadIdx.x;
    int p0 = blockIdx.x * 128;
    __shared__ float xs[128 * 6];
    __shared__ int   ms[128];
    for (int idx = c; idx < 768; idx += 128) xs[idx] = x[p0 * 6 + idx];
    ms[c] = mask[p0 + c];
    __syncthreads();
    float w0 = W1[0*128+c], w1 = W1[1*128+c], w2 = W1[2*128+c];
    float w3 = W1[3*128+c], w4 = W1[4*128+c], w5 = W1[5*128+c];
    float bb = b1[c];
    float s = 0.f, ss = 0.f; int cnt = 0;
    for (int i = 0; i < 128; i++) {
        const float* xp = &xs[i * 6];
        float t = bb + xp[0]*w0 + xp[1]*w1 + xp[2]*w2 + xp[3]*w3 + xp[4]*w4 + xp[5]*w5;
        g_h[(size_t)(p0 + i) * 128 + c] = t;
        if (ms[i]) { s += t; ss += t * t; cnt++; }
    }
    atomicAdd(&g_sum1[c], s);
    atomicAdd(&g_ss1[c],  ss);
    if (c == 0) atomicAdd(&g_cnt, (float)cnt);
}

__global__ void k_fin1(const float* __restrict__ g1, const float* __restrict__ be1) {
    int c = threadIdx.x;
    float cnt  = g_cnt;
    float mean = g_sum1[c] / cnt;
    float var  = g_ss1[c] / cnt - mean * mean;
    float sc   = g1[c] * rsqrtf(var + EPS);
    g_scale1[c] = sc; g_shift1[c] = be1[c] - mean * sc;
}
__global__ void k_fin2(const float* __restrict__ g2, const float* __restrict__ be2) {
    int c = threadIdx.x;
    float cnt  = g_cnt;
    float mean = g_sum2[c] / cnt;
    float var  = g_ss2[c] / cnt - mean * mean;
    float sc   = g2[c] * rsqrtf(var + EPS);
    g_scale2[c] = sc; g_shift2[c] = be2[c] - mean * sc;
}

__global__ void k_pb(const float* __restrict__ W3, const float* __restrict__ b3) {
    int b = blockIdx.x, j = threadIdx.x;
    __shared__ float pl[256];
    pl[j] = g_pooled[b * 256 + j];
    __syncthreads();
    float s = b3[j];
#pragma unroll 4
    for (int k = 0; k < 256; k++) s += pl[k] * W3[(256 + k) * 256 + j];
    g_pb[b * 256 + j] = s;
}

// ---------------- tensor GEMM: 128x128 tile, BK=32, ldmatrix + bf16 split ----
// AMODE: 1 = A fp32, apply relu(a*sc[k]+sh[k]), split on the fly
//        0 = A pre-split bf16 hi/lo (row-major [m][KTOT])
// EMODE: 0 = y: (+bias)*mask, store split bf16, fused max-pool -> redT(pooled)
//        1 = h2: +bias[batch*256+col], store fp32, fused masked stats
//        2 = out: (+bias)*mask, max over rows -> redT[batch*128+col]
template<int KTOT, int AMODE, int EMODE>
__global__ void __launch_bounds__(256, 2) k_tc(
    const float* __restrict__ Af,
    const __nv_bfloat16* __restrict__ Ahi, const __nv_bfloat16* __restrict__ Alo,
    const __nv_bfloat16* __restrict__ Bhi, const __nv_bfloat16* __restrict__ Blo,
    const float* __restrict__ bias, const int* __restrict__ maskp,
    const float* __restrict__ scA, const float* __restrict__ shA,
    float* __restrict__ Cf,
    __nv_bfloat16* __restrict__ Chi, __nv_bfloat16* __restrict__ Clo,
    float* __restrict__ redT)
{
    __shared__ __nv_bfloat16 As_h[128][40], As_l[128][40];
    __shared__ __nv_bfloat16 Bs_h[128][40], Bs_l[128][40];
    __shared__ float scs[256], shs[256], bias_s[128];
    __shared__ float redA[128], redB[128];
    __shared__ int   pool_s[128];

    const int tid  = threadIdx.x;
    const int wid  = tid >> 5;
    const int lane = tid & 31;
    const int warp_m = wid & 3;      // 4 -> 32 rows each
    const int warp_n = wid >> 2;     // 2 -> 64 cols each
    const int g  = lane >> 2, t4 = lane & 3;
    const int rowBase = blockIdx.y * 128;
    const int colBase = blockIdx.x * 128;
    const int batch   = rowBase >> 9;

    if (AMODE == 1) {
        for (int i = tid; i < KTOT; i += 256) { scs[i] = scA[i]; shs[i] = shA[i]; }
    }
    if (tid < 128) {
        bias_s[tid] = bias[(EMODE == 1 ? batch * 256 : 0) + colBase + tid];
    }

    float acc[2][8][4];
#pragma unroll
    for (int i = 0; i < 2; i++)
#pragma unroll
        for (int j = 0; j < 8; j++)
#pragma unroll
            for (int l = 0; l < 4; l++) acc[i][j][l] = 0.f;

    // loader mapping: thread -> (row, khalf)
    const int ldRow = tid >> 1;
    const int ldKh  = (tid & 1) * 16;

    // ldmatrix lane offsets
    const int lrow = lane & 7, lsel = lane >> 3;
    const int aRowOff = (lsel & 1) * 8 + lrow, aKOff = (lsel >> 1) * 8;
    const int bRowOff = (lsel >> 1) * 8 + lrow, bKOff = (lsel & 1) * 8;

    const uint32_t sAh = smem_u32(&As_h[0][0]), sAl = smem_u32(&As_l[0][0]);
    const uint32_t sBh = smem_u32(&Bs_h[0][0]), sBl = smem_u32(&Bs_l[0][0]);

    __syncthreads();

    for (int k0 = 0; k0 < KTOT; k0 += 32) {
        // ---- load A (128 x 32) ----
        if (AMODE == 1) {
            const float* ap = Af + (size_t)(rowBase + ldRow) * KTOT + k0 + ldKh;
            float v[16];
#pragma unroll
            for (int q = 0; q < 4; q++) {
                float4 x4 = *(const float4*)(ap + q * 4);
                v[q*4+0] = x4.x; v[q*4+1] = x4.y; v[q*4+2] = x4.z; v[q*4+3] = x4.w;
            }
            float hi[16], lo[16];
#pragma unroll
            for (int j = 0; j < 16; j++) {
                float t = fmaxf(v[j] * scs[k0 + ldKh + j] + shs[k0 + ldKh + j], 0.f);
                float h = __bfloat162float(__float2bfloat16(t));
                hi[j] = t; lo[j] = t - h;
            }
            uint4 H0 = make_uint4(pk(hi[0],hi[1]), pk(hi[2],hi[3]), pk(hi[4],hi[5]), pk(hi[6],hi[7]));
            uint4 H1 = make_uint4(pk(hi[8],hi[9]), pk(hi[10],hi[11]), pk(hi[12],hi[13]), pk(hi[14],hi[15]));
            uint4 L0 = make_uint4(pk(lo[0],lo[1]), pk(lo[2],lo[3]), pk(lo[4],lo[5]), pk(lo[6],lo[7]));
            uint4 L1 = make_uint4(pk(lo[8],lo[9]), pk(lo[10],lo[11]), pk(lo[12],lo[13]), pk(lo[14],lo[15]));
            *(uint4*)&As_h[ldRow][ldKh]     = H0;
            *(uint4*)&As_h[ldRow][ldKh + 8] = H1;
            *(uint4*)&As_l[ldRow][ldKh]     = L0;
            *(uint4*)&As_l[ldRow][ldKh + 8] = L1;
        } else {
            size_t go = (size_t)(rowBase + ldRow) * KTOT + k0 + ldKh;
            *(uint4*)&As_h[ldRow][ldKh]     = *(const uint4*)(Ahi + go);
            *(uint4*)&As_h[ldRow][ldKh + 8] = *(const uint4*)(Ahi + go + 8);
            *(uint4*)&As_l[ldRow][ldKh]     = *(const uint4*)(Alo + go);
            *(uint4*)&As_l[ldRow][ldKh + 8] = *(const uint4*)(Alo + go + 8);
        }
        // ---- load B (128 x 32, pre-split, [n][KTOT]) ----
        {
            size_t go = (size_t)(colBase + ldRow) * KTOT + k0 + ldKh;
            *(uint4*)&Bs_h[ldRow][ldKh]     = *(const uint4*)(Bhi + go);
            *(uint4*)&Bs_h[ldRow][ldKh + 8] = *(const uint4*)(Bhi + go + 8);
            *(uint4*)&Bs_l[ldRow][ldKh]     = *(const uint4*)(Blo + go);
            *(uint4*)&Bs_l[ldRow][ldKh + 8] = *(const uint4*)(Blo + go + 8);
        }
        __syncthreads();

#pragma unroll
        for (int kk = 0; kk < 32; kk += 16) {
            uint32_t ah[2][4], al[2][4];
#pragma unroll
            for (int mt = 0; mt < 2; mt++) {
                int ar = warp_m * 32 + mt * 16;
                uint32_t off = (uint32_t)((ar + aRowOff) * 40 + kk + aKOff) * 2;
                ldsm4(ah[mt], sAh + off);
                ldsm4(al[mt], sAl + off);
            }
#pragma unroll
            for (int ng = 0; ng < 4; ng++) {
                int bn = warp_n * 64 + ng * 16;
                uint32_t off = (uint32_t)((bn + bRowOff) * 40 + kk + bKOff) * 2;
                uint32_t bh[4], bl[4];
                ldsm4(bh, sBh + off);
                ldsm4(bl, sBl + off);
#pragma unroll
                for (int hf = 0; hf < 2; hf++) {
                    int nt = ng * 2 + hf;
                    uint32_t b0 = bh[hf * 2], b1 = bh[hf * 2 + 1];
                    uint32_t c0 = bl[hf * 2], c1 = bl[hf * 2 + 1];
#pragma unroll
                    for (int mt = 0; mt < 2; mt++) {
                        mma_bf16(acc[mt][nt], ah[mt], b0, b1);
                        mma_bf16(acc[mt][nt], ah[mt], c0, c1);
                        mma_bf16(acc[mt][nt], al[mt], b0, b1);
                    }
                }
            }
        }
        __syncthreads();
    }

    // ---------------- epilogue ----------------
    if (tid < 128) { pool_s[tid] = 0; redA[tid] = 0.f; redB[tid] = 0.f; }
    __syncthreads();

    if (EMODE == 0) {
#pragma unroll
        for (int mt = 0; mt < 2; mt++) {
            int r0 = rowBase + warp_m * 32 + mt * 16 + g;
            int r1 = r0 + 8;
            float m0 = (maskp[r0] != 0) ? 1.f : 0.f;
            float m1 = (maskp[r1] != 0) ? 1.f : 0.f;
#pragma unroll
            for (int nt = 0; nt < 8; nt++) {
                int lc = warp_n * 64 + nt * 8 + 2 * t4;
                int c0 = colBase + lc;
                float bx = bias_s[lc], by = bias_s[lc + 1];
                float v00 = (acc[mt][nt][0] + bx) * m0;
                float v01 = (acc[mt][nt][1] + by) * m0;
                float v10 = (acc[mt][nt][2] + bx) * m1;
                float v11 = (acc[mt][nt][3] + by) * m1;
                float h00 = __bfloat162float(__float2bfloat16(v00));
                float h01 = __bfloat162float(__float2bfloat16(v01));
                float h10 = __bfloat162float(__float2bfloat16(v10));
                float h11 = __bfloat162float(__float2bfloat16(v11));
                *(uint32_t*)&Chi[(size_t)r0 * 256 + c0] = pk(v00, v01);
                *(uint32_t*)&Chi[(size_t)r1 * 256 + c0] = pk(v10, v11);
                *(uint32_t*)&Clo[(size_t)r0 * 256 + c0] = pk(v00 - h00, v01 - h01);
                *(uint32_t*)&Clo[(size_t)r1 * 256 + c0] = pk(v10 - h10, v11 - h11);
                float p0 = fmaxf(v00, v10), p1 = fmaxf(v01, v11);
                if (p0 > 0.f) atomicMax(&pool_s[lc],     __float_as_int(p0));
                if (p1 > 0.f) atomicMax(&pool_s[lc + 1], __float_as_int(p1));
            }
        }
        __syncthreads();
        if (tid < 128) {
            int v = pool_s[tid];
            if (v > 0) atomicMax((int*)&redT[batch * 256 + colBase + tid], v);
        }
    } else if (EMODE == 1) {
#pragma unroll
        for (int nt = 0; nt < 8; nt++) {
            int lc = warp_n * 64 + nt * 8 + 2 * t4;
            int c0 = colBase + lc;
            float bx = bias_s[lc], by = bias_s[lc + 1];
            float s0 = 0.f, s1 = 0.f, q0 = 0.f, q1 = 0.f;
#pragma unroll
            for (int mt = 0; mt < 2; mt++) {
                int r0 = rowBase + warp_m * 32 + mt * 16 + g;
                int r1 = r0 + 8;
                float v00 = acc[mt][nt][0] + bx;
                float v01 = acc[mt][nt][1] + by;
                float v10 = acc[mt][nt][2] + bx;
                float v11 = acc[mt][nt][3] + by;
                *(float2*)&Cf[(size_t)r0 * 256 + c0] = make_float2(v00, v01);
                *(float2*)&Cf[(size_t)r1 * 256 + c0] = make_float2(v10, v11);
                if (maskp[r0]) { s0 += v00; s1 += v01; q0 += v00*v00; q1 += v01*v01; }
                if (maskp[r1]) { s0 += v10; s1 += v11; q0 += v10*v10; q1 += v11*v11; }
            }
            atomicAdd(&redA[lc],     s0);
            atomicAdd(&redA[lc + 1], s1);
            atomicAdd(&redB[lc],     q0);
            atomicAdd(&redB[lc + 1], q1);
        }
        __syncthreads();
        if (tid < 128) {
            atomicAdd(&g_sum2[colBase + tid], redA[tid]);
            atomicAdd(&g_ss2[colBase + tid],  redB[tid]);
        }
    } else {
#pragma unroll
        for (int nt = 0; nt < 8; nt++) {
            int lc = warp_n * 64 + nt * 8 + 2 * t4;
            float bx = bias_s[lc], by = bias_s[lc + 1];
            float p0 = 0.f, p1 = 0.f;
#pragma unroll
            for (int mt = 0; mt < 2; mt++) {
                int r0 = rowBase + warp_m * 32 + mt * 16 + g;
                int r1 = r0 + 8;
                float m0 = (maskp[r0] != 0) ? 1.f : 0.f;
                float m1 = (maskp[r1] != 0) ? 1.f : 0.f;
                p0 = fmaxf(p0, (acc[mt][nt][0] + bx) * m0);
                p1 = fmaxf(p1, (acc[mt][nt][1] + by) * m0);
                p0 = fmaxf(p0, (acc[mt][nt][2] + bx) * m1);
                p1 = fmaxf(p1, (acc[mt][nt][3] + by) * m1);
            }
            if (p0 > 0.f) atomicMax(&pool_s[lc],     __float_as_int(p0));
            if (p1 > 0.f) atomicMax(&pool_s[lc + 1], __float_as_int(p1));
        }
        __syncthreads();
        if (tid < 128) {
            int v = pool_s[tid];
            if (v > 0) atomicMax((int*)&redT[batch * 128 + tid], v);
        }
    }
}

// ---------------- launch ----------------
extern "C" void kernel_launch(void* const* d_in, const int* in_sizes, int n_in,
                              void* d_out, int out_size) {
    const float* x   = (const float*)d_in[0];
    const int*   mask= (const int*)  d_in[1];
    const float* W1  = (const float*)d_in[2];
    const float* b1  = (const float*)d_in[3];
    const float* g1  = (const float*)d_in[4];
    const float* be1 = (const float*)d_in[5];
    const float* W2  = (const float*)d_in[6];
    const float* b2  = (const float*)d_in[7];
    const float* W3  = (const float*)d_in[8];
    const float* b3  = (const float*)d_in[9];
    const float* g2  = (const float*)d_in[10];
    const float* be2 = (const float*)d_in[11];
    const float* W4  = (const float*)d_in[12];
    const float* b4  = (const float*)d_in[13];
    float* out = (float*)d_out;

    float *p_h, *p_h2, *p_pooled, *p_pb, *p_sc1, *p_sh1, *p_sc2, *p_sh2;
    __nv_bfloat16 *p_yhi, *p_ylo, *p_w2hi, *p_w2lo, *p_w3hi, *p_w3lo, *p_w4hi, *p_w4lo;
    cudaGetSymbolAddress((void**)&p_h,      g_h);
    cudaGetSymbolAddress((void**)&p_h2,     g_h2);
    cudaGetSymbolAddress((void**)&p_pooled, g_pooled);
    cudaGetSymbolAddress((void**)&p_pb,     g_pb);
    cudaGetSymbolAddress((void**)&p_sc1,    g_scale1);
    cudaGetSymbolAddress((void**)&p_sh1,    g_shift1);
    cudaGetSymbolAddress((void**)&p_sc2,    g_scale2);
    cudaGetSymbolAddress((void**)&p_sh2,    g_shift2);
    cudaGetSymbolAddress((void**)&p_yhi,    g_yhi);
    cudaGetSymbolAddress((void**)&p_ylo,    g_ylo);
    cudaGetSymbolAddress((void**)&p_w2hi,   g_w2hi);
    cudaGetSymbolAddress((void**)&p_w2lo,   g_w2lo);
    cudaGetSymbolAddress((void**)&p_w3hi,   g_w3hi);
    cudaGetSymbolAddress((void**)&p_w3lo,   g_w3lo);
    cudaGetSymbolAddress((void**)&p_w4hi,   g_w4hi);
    cudaGetSymbolAddress((void**)&p_w4lo,   g_w4lo);

    k_init  <<<512, 256>>>(out, p_pooled);
    k_wprep<128,256><<<256, 128>>>(W2, p_w2hi, p_w2lo);
    k_wprep<256,256><<<256, 128>>>(W3, p_w3hi, p_w3lo);
    k_wprep<256,128><<<128, 256>>>(W4, p_w4hi, p_w4lo);
    k_h_stats<<<2048, 128>>>(x, mask, W1, b1);
    k_fin1  <<<1, 128>>>(g1, be1);

    // GEMM2: y = (relu(bn1(g_h)) @ W2 + b2)*mask  [+ fused max-pool]
    k_tc<128,1,0><<<dim3(2, 2048), 256>>>(p_h, nullptr, nullptr, p_w2hi, p_w2lo,
        b2, mask, p_sc1, p_sh1, nullptr, p_yhi, p_ylo, p_pooled);
    k_pb    <<<512, 256>>>(W3, b3);
    // GEMM3: h2 = y @ W3[:256] + pb[batch]  [+ fused BN2 stats]
    k_tc<256,0,1><<<dim3(2, 2048), 256>>>(nullptr, p_yhi, p_ylo, p_w3hi, p_w3lo,
        p_pb, mask, nullptr, nullptr, p_h2, nullptr, nullptr, nullptr);
    k_fin2  <<<1, 256>>>(g2, be2);
    // GEMM4: out = max_n ((relu(bn2(h2)) @ W4 + b4)*mask)
    k_tc<256,1,2><<<dim3(1, 2048), 256>>>(p_h2, nullptr, nullptr, p_w4hi, p_w4lo,
        b4, mask, p_sc2, p_sh2, nullptr, nullptr, nullptr, out);
}

// round 5
// speedup vs baseline: 1.9117x; 1.0348x over previous
#include <cuda_runtime.h>
#include <cuda_bf16.h>
#include <cstdint>

#define EPS 1e-5f
#define NB  512
#define NP  512
#define MT  (NB*NP)

// ---------------- device scratch ----------------
__device__ float g_h2[(size_t)MT * 256];
__device__ __nv_bfloat16 g_yhi[(size_t)MT * 256];
__device__ __nv_bfloat16 g_ylo[(size_t)MT * 256];
__device__ __nv_bfloat16 g_w2hi[256*128], g_w2lo[256*128];
__device__ __nv_bfloat16 g_w3hi[256*256], g_w3lo[256*256];
__device__ __nv_bfloat16 g_w4hi[128*256], g_w4lo[128*256];
__device__ float g_pooled[NB*256];
__device__ float g_pb[NB*256];
__device__ float g_sum1[128], g_ss1[128];
__device__ float g_sum2[256], g_ss2[256];
__device__ float g_cnt;
__device__ float g_scale1[128], g_shift1[128];
__device__ float g_scale2[256], g_shift2[256];

// ---------------- helpers ----------------
__device__ __forceinline__ uint32_t smem_u32(const void* p) {
    uint32_t a;
    asm("{ .reg .u64 t; cvta.to.shared.u64 t, %1; cvt.u32.u64 %0, t; }" : "=r"(a) : "l"(p));
    return a;
}
__device__ __forceinline__ void ldsm4(uint32_t* r, uint32_t addr) {
    asm volatile("ldmatrix.sync.aligned.m8n8.x4.shared.b16 {%0,%1,%2,%3}, [%4];"
        : "=r"(r[0]), "=r"(r[1]), "=r"(r[2]), "=r"(r[3]) : "r"(addr));
}
__device__ __forceinline__ void mma_bf16(float* c, const uint32_t* a, uint32_t b0, uint32_t b1) {
    asm volatile(
        "mma.sync.aligned.m16n8k16.row.col.f32.bf16.bf16.f32 "
        "{%0,%1,%2,%3},{%4,%5,%6,%7},{%8,%9},{%0,%1,%2,%3};\n"
        : "+f"(c[0]), "+f"(c[1]), "+f"(c[2]), "+f"(c[3])
        : "r"(a[0]), "r"(a[1]), "r"(a[2]), "r"(a[3]), "r"(b0), "r"(b1));
}
__device__ __forceinline__ uint32_t pk(float a, float b) {
    __nv_bfloat162 t;
    t.x = __float2bfloat16(a); t.y = __float2bfloat16(b);
    return *(uint32_t*)&t;
}
__device__ __forceinline__ void cpa16(uint32_t dst, const void* src) {
    asm volatile("cp.async.cg.shared.global [%0], [%1], 16;" :: "r"(dst), "l"(src));
}
#define CPA_COMMIT() asm volatile("cp.async.commit_group;" ::: "memory")
#define CPA_WAIT0()  asm volatile("cp.async.wait_group 0;"  ::: "memory")

// ---------------- small kernels ----------------
__global__ void k_init(float* __restrict__ out, float* __restrict__ pooled) {
    int i = blockIdx.x * blockDim.x + threadIdx.x;
    if (i < 65536)  out[i] = 0.f;
    if (i < 131072) pooled[i] = 0.f;
    if (i < 128) { g_sum1[i] = 0.f; g_ss1[i] = 0.f; }
    if (i < 256) { g_sum2[i] = 0.f; g_ss2[i] = 0.f; }
    if (i == 0)  g_cnt = 0.f;
}

template<int K, int N>
__global__ void k_wprep(const float* __restrict__ W,
                        __nv_bfloat16* __restrict__ Whi, __nv_bfloat16* __restrict__ Wlo) {
    int n = blockIdx.x;
    for (int k = threadIdx.x; k < K; k += blockDim.x) {
        float v = W[(size_t)k * N + n];
        __nv_bfloat16 h = __float2bfloat16(v);
        Whi[(size_t)n * K + k] = h;
        Wlo[(size_t)n * K + k] = __float2bfloat16(v - __bfloat162float(h));
    }
}

// stats over h = x@W1+b1 (computed on the fly; h is NOT stored)
__global__ void k_h_stats(const float* __restrict__ x, const int* __restrict__ mask,
                          const float* __restrict__ W1, const float* __restrict__ b1) {
    int c  = threadIdx.x;
    int p0 = blockIdx.x * 128;
    __shared__ float xs[128 * 6];
    __shared__ int   ms[128];
    for (int idx = c; idx < 768; idx += 128) xs[idx] = x[p0 * 6 + idx];
    ms[c] = mask[p0 + c];
    __syncthreads();
    float w0 = W1[0*128+c], w1 = W1[1*128+c], w2 = W1[2*128+c];
    float w3 = W1[3*128+c], w4 = W1[4*128+c], w5 = W1[5*128+c];
    float bb = b1[c];
    float s = 0.f, ss = 0.f; int cnt = 0;
    for (int i = 0; i < 128; i++) {
        if (!ms[i]) continue;
        const float* xp = &xs[i * 6];
        float t = bb + xp[0]*w0 + xp[1]*w1 + xp[2]*w2 + xp[3]*w3 + xp[4]*w4 + xp[5]*w5;
        s += t; ss += t * t; cnt++;
    }
    atomicAdd(&g_sum1[c], s);
    atomicAdd(&g_ss1[c],  ss);
    if (c == 0) atomicAdd(&g_cnt, (float)cnt);
}

__global__ void k_fin1(const float* __restrict__ g1, const float* __restrict__ be1) {
    int c = threadIdx.x;
    float cnt  = g_cnt;
    float mean = g_sum1[c] / cnt;
    float var  = g_ss1[c] / cnt - mean * mean;
    float sc   = g1[c] * rsqrtf(var + EPS);
    g_scale1[c] = sc; g_shift1[c] = be1[c] - mean * sc;
}
__global__ void k_fin2(const float* __restrict__ g2, const float* __restrict__ be2) {
    int c = threadIdx.x;
    float cnt  = g_cnt;
    float mean = g_sum2[c] / cnt;
    float var  = g_ss2[c] / cnt - mean * mean;
    float sc   = g2[c] * rsqrtf(var + EPS);
    g_scale2[c] = sc; g_shift2[c] = be2[c] - mean * sc;
}

__global__ void k_pb(const float* __restrict__ W3, const float* __restrict__ b3) {
    int b = blockIdx.x, j = threadIdx.x;
    __shared__ float pl[256];
    pl[j] = g_pooled[b * 256 + j];
    __syncthreads();
    float s = b3[j];
#pragma unroll 4
    for (int k = 0; k < 256; k++) s += pl[k] * W3[(256 + k) * 256 + j];
    g_pb[b * 256 + j] = s;
}

// ---------------- pipelined tensor GEMM, tile 128 x NTILE, BK=32 ----------
// AMODE: 0 = A pre-split bf16 hi/lo (cp.async)
//        1 = A fp32 LDG + relu(a*sc+sh) transform + split
//        2 = A computed from x@W1+b1 then relu(bn1) (GEMM2; no A gmem traffic)
// EMODE: 0 = y: (+bias)*mask, store split bf16, fused max-pool -> redT
//        1 = h2: +bias[batch*256+col], store fp32, fused masked stats
//        2 = out: (+bias)*mask, max over rows -> redT[batch*128+col]
template<int KTOT, int NTILE, int AMODE, int EMODE>
__global__ void __launch_bounds__(NTILE * 2, 1) k_tc(
    const float* __restrict__ Af, const float* __restrict__ xin,
    const __nv_bfloat16* __restrict__ Ahi, const __nv_bfloat16* __restrict__ Alo,
    const __nv_bfloat16* __restrict__ Bhi, const __nv_bfloat16* __restrict__ Blo,
    const float* __restrict__ bias, const int* __restrict__ maskp,
    const float* __restrict__ scA, const float* __restrict__ shA,
    const float* __restrict__ W1, const float* __restrict__ b1,
    float* __restrict__ Cf,
    __nv_bfloat16* __restrict__ Chi, __nv_bfloat16* __restrict__ Clo,
    float* __restrict__ redT)
{
    constexpr int THREADS = NTILE * 2;
    constexpr int C = KTOT / 32;
    constexpr int ABUF  = 128 * 40 * 2;     // bytes per A buffer (one half)
    constexpr int BBUFB = NTILE * 40 * 2;   // bytes per B buffer (one half)

    extern __shared__ __align__(1024) char sm[];
    const uint32_t sb  = smem_u32(sm);
    const uint32_t pAh = sb;
    const uint32_t pAl = sb + 2 * ABUF;
    const uint32_t pBh = sb + 4 * ABUF;
    const uint32_t pBl = pBh + 2 * BBUFB;
    float* fb     = (float*)(sm + 4 * ABUF + 4 * BBUFB);
    float* bias_s = fb;                  // [NTILE]
    float* redA   = fb + NTILE;          // [NTILE]
    float* redB   = fb + 2 * NTILE;      // [NTILE]
    int*   pool_s = (int*)redA;
    float* xs     = fb + 3 * NTILE;      // [768]
    float* w1s    = xs + 768;            // [768]
    float* b1s    = w1s + 768;           // [128]
    float* scs    = b1s + 128;           // [KTOT]
    float* shs    = scs + KTOT;          // [KTOT]

    const int tid  = threadIdx.x;
    const int wid  = tid >> 5;
    const int lane = tid & 31;
    const int warp_m = wid & 3;
    const int warp_n = wid >> 2;
    const int g  = lane >> 2, t4 = lane & 3;
    const int rowBase = blockIdx.x * 128;
    const int batch   = rowBase >> 9;

    // ---- preload constant smem ----
    if (AMODE >= 1) {
        for (int i = tid; i < KTOT; i += THREADS) { scs[i] = scA[i]; shs[i] = shA[i]; }
    }
    if (AMODE == 2) {
        for (int i = tid; i < 768; i += THREADS) {
            xs[i]  = xin[(size_t)rowBase * 6 + i];
            w1s[i] = W1[i];
        }
        if (tid < 128) b1s[tid] = b1[tid];
    }
    if (tid < NTILE) bias_s[tid] = bias[(EMODE == 1 ? batch * 256 : 0) + tid];
    __syncthreads();

    float acc[2][8][4];
#pragma unroll
    for (int i = 0; i < 2; i++)
#pragma unroll
        for (int j = 0; j < 8; j++)
#pragma unroll
            for (int l = 0; l < 4; l++) acc[i][j][l] = 0.f;

    // loader mapping (A): idx over 128 rows x 4 kq
    const int aIdx = tid;                 // THREADS >= 512? For 256 threads: 2 items
    // ldmatrix lane offsets
    const int lrow = lane & 7, lsel = lane >> 3;
    const int aRowOff = (lsel & 1) * 8 + lrow, aKOff = (lsel >> 1) * 8;
    const int bRowOff = (lsel >> 1) * 8 + lrow, bKOff = (lsel & 1) * 8;

    // ---- stage helpers (lambdas) ----
    auto stageA_async = [&](int k0, int buf) {   // AMODE==0
#pragma unroll
        for (int i = 0; i < (512 + THREADS - 1) / THREADS; i++) {
            int idx = aIdx + i * THREADS;
            if (idx < 512) {
                int row = idx >> 2, k8 = (idx & 3) * 8;
                uint32_t so = (uint32_t)(row * 40 + k8) * 2;
                size_t go = (size_t)(rowBase + row) * KTOT + k0 + k8;
                cpa16(pAh + buf * ABUF + so, Ahi + go);
                cpa16(pAl + buf * ABUF + so, Alo + go);
            }
        }
    };
    auto stageA_compute = [&](int k0, int buf) {  // AMODE==2 (KTOT==128)
#pragma unroll
        for (int i = 0; i < (512 + THREADS - 1) / THREADS; i++) {
            int idx = aIdx + i * THREADS;
            if (idx < 512) {
                int row = idx >> 2, k8 = (idx & 3) * 8;
                float xr[6];
#pragma unroll
                for (int d = 0; d < 6; d++) xr[d] = xs[row * 6 + d];
                uint32_t H[4], L[4];
#pragma unroll
                for (int jp = 0; jp < 4; jp++) {
                    float tv[2];
#pragma unroll
                    for (int q = 0; q < 2; q++) {
                        int kk = k0 + k8 + jp * 2 + q;
                        float t = b1s[kk];
#pragma unroll
                        for (int d = 0; d < 6; d++) t += xr[d] * w1s[d * 128 + kk];
                        t = fmaxf(t * scs[kk] + shs[kk], 0.f);
                        tv[q] = t;
                    }
                    float h0 = __bfloat162float(__float2bfloat16(tv[0]));
                    float h1 = __bfloat162float(__float2bfloat16(tv[1]));
                    H[jp] = pk(tv[0], tv[1]);
                    L[jp] = pk(tv[0] - h0, tv[1] - h1);
                }
                uint32_t so = (uint32_t)(row * 40 + k8) * 2;
                *(uint4*)(sm + (pAh - sb) + buf * ABUF + so) = make_uint4(H[0], H[1], H[2], H[3]);
                *(uint4*)(sm + (pAl - sb) + buf * ABUF + so) = make_uint4(L[0], L[1], L[2], L[3]);
            }
        }
    };
    auto stageB = [&](int k0, int buf) {
#pragma unroll
        for (int i = 0; i < (NTILE * 4) / THREADS; i++) {
            int idx = tid + i * THREADS;
            int row = idx >> 2, k8 = (idx & 3) * 8;
            uint32_t so = (uint32_t)(row * 40 + k8) * 2;
            size_t go = (size_t)row * KTOT + k0 + k8;
            cpa16(pBh + buf * BBUFB + so, Bhi + go);
            cpa16(pBl + buf * BBUFB + so, Blo + go);
        }
    };

    // AMODE==1 prefetch registers (16 floats per thread, 256 threads)
    float pf[AMODE == 1 ? 16 : 1];
    const int ldRow1 = tid >> 1, ldKh1 = (tid & 1) * 16;
    auto ldgA1 = [&](int k0) {
        const float* ap = Af + (size_t)(rowBase + ldRow1) * KTOT + k0 + ldKh1;
#pragma unroll
        for (int q = 0; q < 4; q++) {
            float4 v = *(const float4*)(ap + q * 4);
            pf[q*4+0] = v.x; pf[q*4+1] = v.y; pf[q*4+2] = v.z; pf[q*4+3] = v.w;
        }
    };
    auto stsA1 = [&](int k0, int buf) {
        uint32_t H[8], L[8];
#pragma unroll
        for (int jp = 0; jp < 8; jp++) {
            float t0 = fmaxf(pf[jp*2]   * scs[k0 + ldKh1 + jp*2]   + shs[k0 + ldKh1 + jp*2],   0.f);
            float t1 = fmaxf(pf[jp*2+1] * scs[k0 + ldKh1 + jp*2+1] + shs[k0 + ldKh1 + jp*2+1], 0.f);
            float h0 = __bfloat162float(__float2bfloat16(t0));
            float h1 = __bfloat162float(__float2bfloat16(t1));
            H[jp] = pk(t0, t1);
            L[jp] = pk(t0 - h0, t1 - h1);
        }
        uint32_t so = (uint32_t)(ldRow1 * 40 + ldKh1) * 2;
        *(uint4*)(sm + (pAh - sb) + buf * ABUF + so)      = make_uint4(H[0], H[1], H[2], H[3]);
        *(uint4*)(sm + (pAh - sb) + buf * ABUF + so + 16) = make_uint4(H[4], H[5], H[6], H[7]);
        *(uint4*)(sm + (pAl - sb) + buf * ABUF + so)      = make_uint4(L[0], L[1], L[2], L[3]);
        *(uint4*)(sm + (pAl - sb) + buf * ABUF + so + 16) = make_uint4(L[4], L[5], L[6], L[7]);
    };

    // ---- prologue: stage chunk 0 ----
    if (AMODE == 0)      stageA_async(0, 0);
    else if (AMODE == 2) stageA_compute(0, 0);
    else               { ldgA1(0); stsA1(0, 0); }
    stageB(0, 0);
    CPA_COMMIT();
    CPA_WAIT0();
    __syncthreads();

    // ---- main loop ----
    for (int c = 0; c < C; c++) {
        const int buf = c & 1;
        if (c + 1 < C) {
            const int k0n = (c + 1) * 32;
            if (AMODE == 0)      stageA_async(k0n, buf ^ 1);
            else if (AMODE == 2) stageA_compute(k0n, buf ^ 1);
            else                 ldgA1(k0n);
            stageB(k0n, buf ^ 1);
            CPA_COMMIT();
        }
        // MMA on buf
#pragma unroll
        for (int kk = 0; kk < 32; kk += 16) {
            uint32_t ah[2][4], al[2][4];
#pragma unroll
            for (int mt = 0; mt < 2; mt++) {
                int ar = warp_m * 32 + mt * 16;
                uint32_t off = (uint32_t)((ar + aRowOff) * 40 + kk + aKOff) * 2;
                ldsm4(ah[mt], pAh + buf * ABUF + off);
                ldsm4(al[mt], pAl + buf * ABUF + off);
            }
#pragma unroll
            for (int ng = 0; ng < 4; ng++) {
                int bn = warp_n * 64 + ng * 16;
                uint32_t off = (uint32_t)((bn + bRowOff) * 40 + kk + bKOff) * 2;
                uint32_t bh[4], bl[4];
                ldsm4(bh, pBh + buf * BBUFB + off);
                ldsm4(bl, pBl + buf * BBUFB + off);
#pragma unroll
                for (int hf = 0; hf < 2; hf++) {
                    int nt = ng * 2 + hf;
                    uint32_t b0 = bh[hf * 2], b1r = bh[hf * 2 + 1];
                    uint32_t c0 = bl[hf * 2], c1r = bl[hf * 2 + 1];
#pragma unroll
                    for (int mt = 0; mt < 2; mt++) {
                        mma_bf16(acc[mt][nt], ah[mt], b0, b1r);
                        mma_bf16(acc[mt][nt], ah[mt], c0, c1r);
                        mma_bf16(acc[mt][nt], al[mt], b0, b1r);
                    }
                }
            }
        }
        if (AMODE == 1 && c + 1 < C) stsA1((c + 1) * 32, buf ^ 1);
        CPA_WAIT0();
        __syncthreads();
    }

    // ---------------- epilogue ----------------
    if (tid < NTILE) { pool_s[tid] = 0; redA[tid] = 0.f; redB[tid] = 0.f; }
    __syncthreads();

    if (EMODE == 0) {
#pragma unroll
        for (int mt = 0; mt < 2; mt++) {
            int r0 = rowBase + warp_m * 32 + mt * 16 + g;
            int r1 = r0 + 8;
            float m0 = (maskp[r0] != 0) ? 1.f : 0.f;
            float m1 = (maskp[r1] != 0) ? 1.f : 0.f;
#pragma unroll
            for (int nt = 0; nt < 8; nt++) {
                int lc = warp_n * 64 + nt * 8 + 2 * t4;
                float bx = bias_s[lc], by = bias_s[lc + 1];
                float v00 = (acc[mt][nt][0] + bx) * m0;
                float v01 = (acc[mt][nt][1] + by) * m0;
                float v10 = (acc[mt][nt][2] + bx) * m1;
                float v11 = (acc[mt][nt][3] + by) * m1;
                float h00 = __bfloat162float(__float2bfloat16(v00));
                float h01 = __bfloat162float(__float2bfloat16(v01));
                float h10 = __bfloat162float(__float2bfloat16(v10));
                float h11 = __bfloat162float(__float2bfloat16(v11));
                *(uint32_t*)&Chi[(size_t)r0 * 256 + lc] = pk(v00, v01);
                *(uint32_t*)&Chi[(size_t)r1 * 256 + lc] = pk(v10, v11);
                *(uint32_t*)&Clo[(size_t)r0 * 256 + lc] = pk(v00 - h00, v01 - h01);
                *(uint32_t*)&Clo[(size_t)r1 * 256 + lc] = pk(v10 - h10, v11 - h11);
                float p0 = fmaxf(v00, v10), p1 = fmaxf(v01, v11);
                if (p0 > 0.f) atomicMax(&pool_s[lc],     __float_as_int(p0));
                if (p1 > 0.f) atomicMax(&pool_s[lc + 1], __float_as_int(p1));
            }
        }
        __syncthreads();
        if (tid < NTILE) {
            int v = pool_s[tid];
            if (v > 0) atomicMax((int*)&redT[batch * 256 + tid], v);
        }
    } else if (EMODE == 1) {
#pragma unroll
        for (int nt = 0; nt < 8; nt++) {
            int lc = warp_n * 64 + nt * 8 + 2 * t4;
            float bx = bias_s[lc], by = bias_s[lc + 1];
            float s0 = 0.f, s1 = 0.f, q0 = 0.f, q1 = 0.f;
#pragma unroll
            for (int mt = 0; mt < 2; mt++) {
                int r0 = rowBase + warp_m * 32 + mt * 16 + g;
                int r1 = r0 + 8;
                float v00 = acc[mt][nt][0] + bx;
                float v01 = acc[mt][nt][1] + by;
                float v10 = acc[mt][nt][2] + bx;
                float v11 = acc[mt][nt][3] + by;
                *(float2*)&Cf[(size_t)r0 * 256 + lc] = make_float2(v00, v01);
                *(float2*)&Cf[(size_t)r1 * 256 + lc] = make_float2(v10, v11);
                if (maskp[r0]) { s0 += v00; s1 += v01; q0 += v00*v00; q1 += v01*v01; }
                if (maskp[r1]) { s0 += v10; s1 += v11; q0 += v10*v10; q1 += v11*v11; }
            }
            atomicAdd(&redA[lc],     s0);
            atomicAdd(&redA[lc + 1], s1);
            atomicAdd(&redB[lc],     q0);
            atomicAdd(&redB[lc + 1], q1);
        }
        __syncthreads();
        if (tid < NTILE) {
            atomicAdd(&g_sum2[tid], redA[tid]);
            atomicAdd(&g_ss2[tid],  redB[tid]);
        }
    } else {
#pragma unroll
        for (int nt = 0; nt < 8; nt++) {
            int lc = warp_n * 64 + nt * 8 + 2 * t4;
            float bx = bias_s[lc], by = bias_s[lc + 1];
            float p0 = 0.f, p1 = 0.f;
#pragma unroll
            for (int mt = 0; mt < 2; mt++) {
                int r0 = rowBase + warp_m * 32 + mt * 16 + g;
                int r1 = r0 + 8;
                float m0 = (maskp[r0] != 0) ? 1.f : 0.f;
                float m1 = (maskp[r1] != 0) ? 1.f : 0.f;
                p0 = fmaxf(p0, (acc[mt][nt][0] + bx) * m0);
                p1 = fmaxf(p1, (acc[mt][nt][1] + by) * m0);
                p0 = fmaxf(p0, (acc[mt][nt][2] + bx) * m1);
                p1 = fmaxf(p1, (acc[mt][nt][3] + by) * m1);
            }
            if (p0 > 0.f) atomicMax(&pool_s[lc],     __float_as_int(p0));
            if (p1 > 0.f) atomicMax(&pool_s[lc + 1], __float_as_int(p1));
        }
        __syncthreads();
        if (tid < NTILE) {
            int v = pool_s[tid];
            if (v > 0) atomicMax((int*)&redT[batch * 128 + tid], v);
        }
    }
}

// smem size formula
static int smem_bytes(int NTILE, int KTOT) {
    int bufs = 4 * (128 * 40 * 2) + 4 * (NTILE * 40 * 2);
    int flts = (3 * NTILE + 768 + 768 + 128 + 2 * KTOT) * 4;
    return bufs + flts;
}

// ---------------- launch ----------------
extern "C" void kernel_launch(void* const* d_in, const int* in_sizes, int n_in,
                              void* d_out, int out_size) {
    const float* x   = (const float*)d_in[0];
    const int*   mask= (const int*)  d_in[1];
    const float* W1  = (const float*)d_in[2];
    const float* b1  = (const float*)d_in[3];
    const float* g1  = (const float*)d_in[4];
    const float* be1 = (const float*)d_in[5];
    const float* W2  = (const float*)d_in[6];
    const float* b2  = (const float*)d_in[7];
    const float* W3  = (const float*)d_in[8];
    const float* b3  = (const float*)d_in[9];
    const float* g2  = (const float*)d_in[10];
    const float* be2 = (const float*)d_in[11];
    const float* W4  = (const float*)d_in[12];
    const float* b4  = (const float*)d_in[13];
    float* out = (float*)d_out;

    float *p_h2, *p_pooled, *p_pb, *p_sc1, *p_sh1, *p_sc2, *p_sh2;
    __nv_bfloat16 *p_yhi, *p_ylo, *p_w2hi, *p_w2lo, *p_w3hi, *p_w3lo, *p_w4hi, *p_w4lo;
    cudaGetSymbolAddress((void**)&p_h2,     g_h2);
    cudaGetSymbolAddress((void**)&p_pooled, g_pooled);
    cudaGetSymbolAddress((void**)&p_pb,     g_pb);
    cudaGetSymbolAddress((void**)&p_sc1,    g_scale1);
    cudaGetSymbolAddress((void**)&p_sh1,    g_shift1);
    cudaGetSymbolAddress((void**)&p_sc2,    g_scale2);
    cudaGetSymbolAddress((void**)&p_sh2,    g_shift2);
    cudaGetSymbolAddress((void**)&p_yhi,    g_yhi);
    cudaGetSymbolAddress((void**)&p_ylo,    g_ylo);
    cudaGetSymbolAddress((void**)&p_w2hi,   g_w2hi);
    cudaGetSymbolAddress((void**)&p_w2lo,   g_w2lo);
    cudaGetSymbolAddress((void**)&p_w3hi,   g_w3hi);
    cudaGetSymbolAddress((void**)&p_w3lo,   g_w3lo);
    cudaGetSymbolAddress((void**)&p_w4hi,   g_w4hi);
    cudaGetSymbolAddress((void**)&p_w4lo,   g_w4lo);

    const int SM2 = smem_bytes(256, 128);
    const int SM3 = smem_bytes(256, 256);
    const int SM4 = smem_bytes(128, 256);
    cudaFuncSetAttribute(k_tc<128,256,2,0>, cudaFuncAttributeMaxDynamicSharedMemorySize, SM2);
    cudaFuncSetAttribute(k_tc<256,256,0,1>, cudaFuncAttributeMaxDynamicSharedMemorySize, SM3);
    cudaFuncSetAttribute(k_tc<256,128,1,2>, cudaFuncAttributeMaxDynamicSharedMemorySize, SM4);

    k_init  <<<512, 256>>>(out, p_pooled);
    k_wprep<128,256><<<256, 128>>>(W2, p_w2hi, p_w2lo);
    k_wprep<256,256><<<256, 128>>>(W3, p_w3hi, p_w3lo);
    k_wprep<256,128><<<128, 256>>>(W4, p_w4hi, p_w4lo);
    k_h_stats<<<2048, 128>>>(x, mask, W1, b1);
    k_fin1  <<<1, 128>>>(g1, be1);

    // GEMM2: y = (relu(bn1(x@W1+b1)) @ W2 + b2)*mask  [+ fused max-pool]; A recomputed from x
    k_tc<128,256,2,0><<<2048, 512, SM2>>>(nullptr, x, nullptr, nullptr, p_w2hi, p_w2lo,
        b2, mask, p_sc1, p_sh1, W1, b1, nullptr, p_yhi, p_ylo, p_pooled);
    k_pb    <<<512, 256>>>(W3, b3);
    // GEMM3: h2 = y @ W3[:256] + pb[batch]  [+ fused BN2 stats]
    k_tc<256,256,0,1><<<2048, 512, SM3>>>(nullptr, nullptr, p_yhi, p_ylo, p_w3hi, p_w3lo,
        p_pb, mask, nullptr, nullptr, nullptr, nullptr, p_h2, nullptr, nullptr, nullptr);
    k_fin2  <<<1, 256>>>(g2, be2);
    // GEMM4: out = max_n ((relu(bn2(h2)) @ W4 + b4)*mask)
    k_tc<256,128,1,2><<<2048, 256, SM4>>>(p_h2, nullptr, nullptr, nullptr, p_w4hi, p_w4lo,
        b4, mask, p_sc2, p_sh2, nullptr, nullptr, nullptr, nullptr, nullptr, out);
}

// round 6
// speedup vs baseline: 2.1587x; 1.1292x over previous
#include <cuda_runtime.h>
#include <cuda_bf16.h>
#include <cstdint>

#define EPS 1e-5f
#define NB  512
#define NP  512
#define MT  (NB*NP)

// ---------------- device scratch ----------------
__device__ float g_h2[(size_t)MT * 256];
__device__ __nv_bfloat16 g_yhi[(size_t)MT * 256];
__device__ __nv_bfloat16 g_ylo[(size_t)MT * 256];
__device__ __nv_bfloat16 g_w2hi[256*128], g_w2lo[256*128];
__device__ __nv_bfloat16 g_w3hi[256*256], g_w3lo[256*256];
__device__ __nv_bfloat16 g_w4hi[128*256], g_w4lo[128*256];
__device__ float g_pooled[NB*256];
__device__ float g_pb[NB*256];
__device__ float g_sum1[128], g_ss1[128];
__device__ float g_sum2[256], g_ss2[256];
__device__ float g_cnt;
__device__ float g_scale1[128], g_shift1[128];
__device__ float g_scale2[256], g_shift2[256];

// ---------------- helpers ----------------
__device__ __forceinline__ uint32_t smem_u32(const void* p) {
    uint32_t a;
    asm("{ .reg .u64 t; cvta.to.shared.u64 t, %1; cvt.u32.u64 %0, t; }" : "=r"(a) : "l"(p));
    return a;
}
__device__ __forceinline__ void ldsm4(uint32_t* r, uint32_t addr) {
    asm volatile("ldmatrix.sync.aligned.m8n8.x4.shared.b16 {%0,%1,%2,%3}, [%4];"
        : "=r"(r[0]), "=r"(r[1]), "=r"(r[2]), "=r"(r[3]) : "r"(addr));
}
__device__ __forceinline__ void mma_bf16(float* c, const uint32_t* a, uint32_t b0, uint32_t b1) {
    asm volatile(
        "mma.sync.aligned.m16n8k16.row.col.f32.bf16.bf16.f32 "
        "{%0,%1,%2,%3},{%4,%5,%6,%7},{%8,%9},{%0,%1,%2,%3};\n"
        : "+f"(c[0]), "+f"(c[1]), "+f"(c[2]), "+f"(c[3])
        : "r"(a[0]), "r"(a[1]), "r"(a[2]), "r"(a[3]), "r"(b0), "r"(b1));
}
__device__ __forceinline__ uint32_t pk(float a, float b) {
    __nv_bfloat162 t;
    t.x = __float2bfloat16(a); t.y = __float2bfloat16(b);
    return *(uint32_t*)&t;
}
__device__ __forceinline__ void cpa16(uint32_t dst, const void* src) {
    asm volatile("cp.async.cg.shared.global [%0], [%1], 16;" :: "r"(dst), "l"(src));
}
#define CPA_COMMIT() asm volatile("cp.async.commit_group;" ::: "memory")
#define CPA_WAIT0()  asm volatile("cp.async.wait_group 0;"  ::: "memory")

// ---------------- small kernels ----------------
__global__ void k_init(float* __restrict__ out, float* __restrict__ pooled) {
    int i = blockIdx.x * blockDim.x + threadIdx.x;
    if (i < 65536)  out[i] = 0.f;
    if (i < 131072) pooled[i] = 0.f;
    if (i < 128) { g_sum1[i] = 0.f; g_ss1[i] = 0.f; }
    if (i < 256) { g_sum2[i] = 0.f; g_ss2[i] = 0.f; }
    if (i == 0)  g_cnt = 0.f;
}

template<int K, int N>
__global__ void k_wprep(const float* __restrict__ W,
                        __nv_bfloat16* __restrict__ Whi, __nv_bfloat16* __restrict__ Wlo) {
    int n = blockIdx.x;
    for (int k = threadIdx.x; k < K; k += blockDim.x) {
        float v = W[(size_t)k * N + n];
        __nv_bfloat16 h = __float2bfloat16(v);
        Whi[(size_t)n * K + k] = h;
        Wlo[(size_t)n * K + k] = __float2bfloat16(v - __bfloat162float(h));
    }
}

// masked stats over h = x@W1+b1 (h never stored)
__global__ void k_h_stats(const float* __restrict__ x, const int* __restrict__ mask,
                          const float* __restrict__ W1, const float* __restrict__ b1) {
    int c  = threadIdx.x;
    int p0 = blockIdx.x * 128;
    __shared__ float xs[128 * 6];
    __shared__ int   ms[128];
    for (int idx = c; idx < 768; idx += 128) xs[idx] = x[p0 * 6 + idx];
    ms[c] = mask[p0 + c];
    __syncthreads();
    float w0 = W1[0*128+c], w1 = W1[1*128+c], w2 = W1[2*128+c];
    float w3 = W1[3*128+c], w4 = W1[4*128+c], w5 = W1[5*128+c];
    float bb = b1[c];
    float s = 0.f, ss = 0.f; int cnt = 0;
    for (int i = 0; i < 128; i++) {
        if (!ms[i]) continue;
        const float* xp = &xs[i * 6];
        float t = bb + xp[0]*w0 + xp[1]*w1 + xp[2]*w2 + xp[3]*w3 + xp[4]*w4 + xp[5]*w5;
        s += t; ss += t * t; cnt++;
    }
    atomicAdd(&g_sum1[c], s);
    atomicAdd(&g_ss1[c],  ss);
    if (c == 0) atomicAdd(&g_cnt, (float)cnt);
}

__global__ void k_fin1(const float* __restrict__ g1, const float* __restrict__ be1) {
    int c = threadIdx.x;
    float cnt  = g_cnt;
    float mean = g_sum1[c] / cnt;
    float var  = g_ss1[c] / cnt - mean * mean;
    float sc   = g1[c] * rsqrtf(var + EPS);
    g_scale1[c] = sc; g_shift1[c] = be1[c] - mean * sc;
}
__global__ void k_fin2(const float* __restrict__ g2, const float* __restrict__ be2) {
    int c = threadIdx.x;
    float cnt  = g_cnt;
    float mean = g_sum2[c] / cnt;
    float var  = g_ss2[c] / cnt - mean * mean;
    float sc   = g2[c] * rsqrtf(var + EPS);
    g_scale2[c] = sc; g_shift2[c] = be2[c] - mean * sc;
}

__global__ void k_pb(const float* __restrict__ W3, const float* __restrict__ b3) {
    int b = blockIdx.x, j = threadIdx.x;
    __shared__ float pl[256];
    pl[j] = g_pooled[b * 256 + j];
    __syncthreads();
    float s = b3[j];
#pragma unroll 4
    for (int k = 0; k < 256; k++) s += pl[k] * W3[(256 + k) * 256 + j];
    g_pb[b * 256 + j] = s;
}

// ---------------- pipelined tensor GEMM, tile 128x128, BK=32, 256 thr, 2 CTA/SM
// AMODE: 0 = A pre-split bf16 hi/lo (cp.async)
//        1 = A fp32 LDG + relu(a*sc+sh) + split
//        2 = A computed from x@W1+b1 then relu(bn1) (GEMM2; no A gmem traffic)
// EMODE: 0 = y: (+bias)*mask, store split bf16, fused max-pool -> redT(pooled)
//        1 = h2: +bias[batch*256+col], store fp32, fused masked stats
//        2 = out: (+bias)*mask, max over rows -> redT[batch*128+col]
#define ABUF 10240              // bytes, one half (hi or lo), one buffer: 128*40*2
#define FB_OFF (8 * ABUF)       // after A(2bufs*2) + B(2bufs*2)

template<int KTOT, int AMODE, int EMODE>
__global__ void __launch_bounds__(256, 2) k_tc(
    const float* __restrict__ Af, const float* __restrict__ xin,
    const __nv_bfloat16* __restrict__ Ahi, const __nv_bfloat16* __restrict__ Alo,
    const __nv_bfloat16* __restrict__ Bhi, const __nv_bfloat16* __restrict__ Blo,
    const float* __restrict__ bias, const int* __restrict__ maskp,
    const float* __restrict__ scA, const float* __restrict__ shA,
    const float* __restrict__ W1, const float* __restrict__ b1,
    float* __restrict__ Cf,
    __nv_bfloat16* __restrict__ Chi, __nv_bfloat16* __restrict__ Clo,
    float* __restrict__ redT)
{
    constexpr int C = KTOT / 32;

    extern __shared__ __align__(128) char sm[];
    const uint32_t sb  = smem_u32(sm);
    const uint32_t pAh = sb;                 // [2][128][40] bf16
    const uint32_t pAl = sb + 2 * ABUF;
    const uint32_t pBh = sb + 4 * ABUF;
    const uint32_t pBl = sb + 6 * ABUF;
    float* fb     = (float*)(sm + FB_OFF);
    float* bias_s = fb;                      // [128]
    float* redA   = fb + 128;                // [128]
    float* redB   = fb + 256;                // [128]
    int*   pool_s = (int*)redA;
    float* xs     = fb + 384;                // [768]
    float* w1s    = xs + 768;                // [768]
    float* b1s    = w1s + 768;               // [128]
    float* scs    = b1s + 128;               // [256]
    float* shs    = scs + 256;               // [256]

    const int tid  = threadIdx.x;
    const int wid  = tid >> 5;
    const int lane = tid & 31;
    const int warp_m = wid & 3;
    const int warp_n = wid >> 2;
    const int g  = lane >> 2, t4 = lane & 3;
    const int colBase = blockIdx.x * 128;
    const int rowBase = blockIdx.y * 128;
    const int batch   = rowBase >> 9;

    if (AMODE >= 1) {
        for (int i = tid; i < KTOT; i += 256) { scs[i] = scA[i]; shs[i] = shA[i]; }
    }
    if (AMODE == 2) {
        for (int i = tid; i < 768; i += 256) {
            xs[i]  = xin[(size_t)rowBase * 6 + i];
            w1s[i] = W1[i];
        }
        if (tid < 128) b1s[tid] = b1[tid];
    }
    if (tid < 128) bias_s[tid] = bias[(EMODE == 1 ? batch * 256 : 0) + colBase + tid];
    __syncthreads();

    float acc[2][8][4];
#pragma unroll
    for (int i = 0; i < 2; i++)
#pragma unroll
        for (int j = 0; j < 8; j++)
#pragma unroll
            for (int l = 0; l < 4; l++) acc[i][j][l] = 0.f;

    // ldmatrix lane offsets
    const int lrow = lane & 7, lsel = lane >> 3;
    const int aRowOff = (lsel & 1) * 8 + lrow, aKOff = (lsel >> 1) * 8;
    const int bRowOff = (lsel >> 1) * 8 + lrow, bKOff = (lsel & 1) * 8;

    auto stageA_async = [&](int k0, int buf) {   // AMODE==0
#pragma unroll
        for (int i = 0; i < 2; i++) {
            int idx = tid + i * 256;
            int row = idx >> 2, k8 = (idx & 3) * 8;
            uint32_t so = (uint32_t)(row * 40 + k8) * 2;
            size_t go = (size_t)(rowBase + row) * KTOT + k0 + k8;
            cpa16(pAh + buf * ABUF + so, Ahi + go);
            cpa16(pAl + buf * ABUF + so, Alo + go);
        }
    };
    auto stageA_compute = [&](int k0, int buf) { // AMODE==2 (KTOT==128)
#pragma unroll
        for (int i = 0; i < 2; i++) {
            int idx = tid + i * 256;
            int row = idx >> 2, k8 = (idx & 3) * 8;
            float xr[6];
#pragma unroll
            for (int d = 0; d < 6; d++) xr[d] = xs[row * 6 + d];
            uint32_t H[4], L[4];
#pragma unroll
            for (int jp = 0; jp < 4; jp++) {
                float tv[2];
#pragma unroll
                for (int q = 0; q < 2; q++) {
                    int kk = k0 + k8 + jp * 2 + q;
                    float t = b1s[kk];
#pragma unroll
                    for (int d = 0; d < 6; d++) t += xr[d] * w1s[d * 128 + kk];
                    tv[q] = fmaxf(t * scs[kk] + shs[kk], 0.f);
                }
                float h0 = __bfloat162float(__float2bfloat16(tv[0]));
                float h1 = __bfloat162float(__float2bfloat16(tv[1]));
                H[jp] = pk(tv[0], tv[1]);
                L[jp] = pk(tv[0] - h0, tv[1] - h1);
            }
            uint32_t so = (uint32_t)(row * 40 + k8) * 2;
            *(uint4*)(sm + (buf * ABUF) + so)            = make_uint4(H[0], H[1], H[2], H[3]);
            *(uint4*)(sm + (2 * ABUF + buf * ABUF) + so) = make_uint4(L[0], L[1], L[2], L[3]);
        }
    };
    auto stageB = [&](int k0, int buf) {
#pragma unroll
        for (int i = 0; i < 2; i++) {
            int idx = tid + i * 256;
            int row = idx >> 2, k8 = (idx & 3) * 8;
            uint32_t so = (uint32_t)(row * 40 + k8) * 2;
            size_t go = (size_t)(colBase + row) * KTOT + k0 + k8;
            cpa16(pBh + buf * ABUF + so, Bhi + go);
            cpa16(pBl + buf * ABUF + so, Blo + go);
        }
    };

    // AMODE==1: register prefetch of A fp32
    float pf[AMODE == 1 ? 16 : 1];
    const int ldRow1 = tid >> 1, ldKh1 = (tid & 1) * 16;
    auto ldgA1 = [&](int k0) {
        const float* ap = Af + (size_t)(rowBase + ldRow1) * KTOT + k0 + ldKh1;
#pragma unroll
        for (int q = 0; q < 4; q++) {
            float4 v = *(const float4*)(ap + q * 4);
            pf[q*4+0] = v.x; pf[q*4+1] = v.y; pf[q*4+2] = v.z; pf[q*4+3] = v.w;
        }
    };
    auto stsA1 = [&](int k0, int buf) {
        uint32_t H[8], L[8];
#pragma unroll
        for (int jp = 0; jp < 8; jp++) {
            float t0 = fmaxf(pf[jp*2]   * scs[k0 + ldKh1 + jp*2]   + shs[k0 + ldKh1 + jp*2],   0.f);
            float t1 = fmaxf(pf[jp*2+1] * scs[k0 + ldKh1 + jp*2+1] + shs[k0 + ldKh1 + jp*2+1], 0.f);
            float h0 = __bfloat162float(__float2bfloat16(t0));
            float h1 = __bfloat162float(__float2bfloat16(t1));
            H[jp] = pk(t0, t1);
            L[jp] = pk(t0 - h0, t1 - h1);
        }
        uint32_t so = (uint32_t)(ldRow1 * 40 + ldKh1) * 2;
        *(uint4*)(sm + (buf * ABUF) + so)                 = make_uint4(H[0], H[1], H[2], H[3]);
        *(uint4*)(sm + (buf * ABUF) + so + 16)            = make_uint4(H[4], H[5], H[6], H[7]);
        *(uint4*)(sm + (2 * ABUF + buf * ABUF) + so)      = make_uint4(L[0], L[1], L[2], L[3]);
        *(uint4*)(sm + (2 * ABUF + buf * ABUF) + so + 16) = make_uint4(L[4], L[5], L[6], L[7]);
    };

    // ---- prologue ----
    if (AMODE == 0)      stageA_async(0, 0);
    else if (AMODE == 2) stageA_compute(0, 0);
    else               { ldgA1(0); stsA1(0, 0); }
    stageB(0, 0);
    CPA_COMMIT();
    CPA_WAIT0();
    __syncthreads();

    // ---- main loop ----
    for (int c = 0; c < C; c++) {
        const int buf = c & 1;
        if (c + 1 < C) {
            const int k0n = (c + 1) * 32;
            if (AMODE == 0)      stageA_async(k0n, buf ^ 1);
            else if (AMODE == 2) stageA_compute(k0n, buf ^ 1);
            else                 ldgA1(k0n);
            stageB(k0n, buf ^ 1);
            CPA_COMMIT();
        }
#pragma unroll
        for (int kk = 0; kk < 32; kk += 16) {
            uint32_t ah[2][4], al[2][4];
#pragma unroll
            for (int mt = 0; mt < 2; mt++) {
                int ar = warp_m * 32 + mt * 16;
                uint32_t off = (uint32_t)((ar + aRowOff) * 40 + kk + aKOff) * 2;
                ldsm4(ah[mt], pAh + buf * ABUF + off);
                ldsm4(al[mt], pAl + buf * ABUF + off);
            }
#pragma unroll
            for (int ng = 0; ng < 4; ng++) {
                int bn = warp_n * 64 + ng * 16;
                uint32_t off = (uint32_t)((bn + bRowOff) * 40 + kk + bKOff) * 2;
                uint32_t bh[4], bl[4];
                ldsm4(bh, pBh + buf * ABUF + off);
                ldsm4(bl, pBl + buf * ABUF + off);
#pragma unroll
                for (int hf = 0; hf < 2; hf++) {
                    int nt = ng * 2 + hf;
                    uint32_t b0 = bh[hf * 2], b1r = bh[hf * 2 + 1];
                    uint32_t c0 = bl[hf * 2], c1r = bl[hf * 2 + 1];
#pragma unroll
                    for (int mt = 0; mt < 2; mt++) {
                        mma_bf16(acc[mt][nt], ah[mt], b0, b1r);
                        mma_bf16(acc[mt][nt], ah[mt], c0, c1r);
                        mma_bf16(acc[mt][nt], al[mt], b0, b1r);
                    }
                }
            }
        }
        if (AMODE == 1 && c + 1 < C) stsA1((c + 1) * 32, buf ^ 1);
        CPA_WAIT0();
        __syncthreads();
    }

    // ---------------- epilogue ----------------
    if (tid < 128) { pool_s[tid] = 0; redA[tid] = 0.f; redB[tid] = 0.f; }
    __syncthreads();

    if (EMODE == 0) {
#pragma unroll
        for (int mt = 0; mt < 2; mt++) {
            int r0 = rowBase + warp_m * 32 + mt * 16 + g;
            int r1 = r0 + 8;
            float m0 = (maskp[r0] != 0) ? 1.f : 0.f;
            float m1 = (maskp[r1] != 0) ? 1.f : 0.f;
#pragma unroll
            for (int nt = 0; nt < 8; nt++) {
                int lc = warp_n * 64 + nt * 8 + 2 * t4;
                int c0 = colBase + lc;
                float bx = bias_s[lc], by = bias_s[lc + 1];
                float v00 = (acc[mt][nt][0] + bx) * m0;
                float v01 = (acc[mt][nt][1] + by) * m0;
                float v10 = (acc[mt][nt][2] + bx) * m1;
                float v11 = (acc[mt][nt][3] + by) * m1;
                float h00 = __bfloat162float(__float2bfloat16(v00));
                float h01 = __bfloat162float(__float2bfloat16(v01));
                float h10 = __bfloat162float(__float2bfloat16(v10));
                float h11 = __bfloat162float(__float2bfloat16(v11));
                *(uint32_t*)&Chi[(size_t)r0 * 256 + c0] = pk(v00, v01);
                *(uint32_t*)&Chi[(size_t)r1 * 256 + c0] = pk(v10, v11);
                *(uint32_t*)&Clo[(size_t)r0 * 256 + c0] = pk(v00 - h00, v01 - h01);
                *(uint32_t*)&Clo[(size_t)r1 * 256 + c0] = pk(v10 - h10, v11 - h11);
                float p0 = fmaxf(v00, v10), p1 = fmaxf(v01, v11);
                if (p0 > 0.f) atomicMax(&pool_s[lc],     __float_as_int(p0));
                if (p1 > 0.f) atomicMax(&pool_s[lc + 1], __float_as_int(p1));
            }
        }
        __syncthreads();
        if (tid < 128) {
            int v = pool_s[tid];
            if (v > 0) atomicMax((int*)&redT[batch * 256 + colBase + tid], v);
        }
    } else if (EMODE == 1) {
#pragma unroll
        for (int nt = 0; nt < 8; nt++) {
            int lc = warp_n * 64 + nt * 8 + 2 * t4;
            int c0 = colBase + lc;
            float bx = bias_s[lc], by = bias_s[lc + 1];
            float s0 = 0.f, s1 = 0.f, q0 = 0.f, q1 = 0.f;
#pragma unroll
            for (int mt = 0; mt < 2; mt++) {
                int r0 = rowBase + warp_m * 32 + mt * 16 + g;
                int r1 = r0 + 8;
                float v00 = acc[mt][nt][0] + bx;
                float v01 = acc[mt][nt][1] + by;
                float v10 = acc[mt][nt][2] + bx;
                float v11 = acc[mt][nt][3] + by;
                *(float2*)&Cf[(size_t)r0 * 256 + c0] = make_float2(v00, v01);
                *(float2*)&Cf[(size_t)r1 * 256 + c0] = make_float2(v10, v11);
                if (maskp[r0]) { s0 += v00; s1 += v01; q0 += v00*v00; q1 += v01*v01; }
                if (maskp[r1]) { s0 += v10; s1 += v11; q0 += v10*v10; q1 += v11*v11; }
            }
            atomicAdd(&redA[lc],     s0);
            atomicAdd(&redA[lc + 1], s1);
            atomicAdd(&redB[lc],     q0);
            atomicAdd(&redB[lc + 1], q1);
        }
        __syncthreads();
        if (tid < 128) {
            atomicAdd(&g_sum2[colBase + tid], redA[tid]);
            atomicAdd(&g_ss2[colBase + tid],  redB[tid]);
        }
    } else {
#pragma unroll
        for (int nt = 0; nt < 8; nt++) {
            int lc = warp_n * 64 + nt * 8 + 2 * t4;
            float bx = bias_s[lc], by = bias_s[lc + 1];
            float p0 = 0.f, p1 = 0.f;
#pragma unroll
            for (int mt = 0; mt < 2; mt++) {
                int r0 = rowBase + warp_m * 32 + mt * 16 + g;
                int r1 = r0 + 8;
                float m0 = (maskp[r0] != 0) ? 1.f : 0.f;
                float m1 = (maskp[r1] != 0) ? 1.f : 0.f;
                p0 = fmaxf(p0, (acc[mt][nt][0] + bx) * m0);
                p1 = fmaxf(p1, (acc[mt][nt][1] + by) * m0);
                p0 = fmaxf(p0, (acc[mt][nt][2] + bx) * m1);
                p1 = fmaxf(p1, (acc[mt][nt][3] + by) * m1);
            }
            if (p0 > 0.f) atomicMax(&pool_s[lc],     __float_as_int(p0));
            if (p1 > 0.f) atomicMax(&pool_s[lc + 1], __float_as_int(p1));
        }
        __syncthreads();
        if (tid < 128) {
            int v = pool_s[tid];
            if (v > 0) atomicMax((int*)&redT[batch * 128 + tid], v);
        }
    }
}

// ---------------- launch ----------------
extern "C" void kernel_launch(void* const* d_in, const int* in_sizes, int n_in,
                              void* d_out, int out_size) {
    const float* x   = (const float*)d_in[0];
    const int*   mask= (const int*)  d_in[1];
    const float* W1  = (const float*)d_in[2];
    const float* b1  = (const float*)d_in[3];
    const float* g1  = (const float*)d_in[4];
    const float* be1 = (const float*)d_in[5];
    const float* W2  = (const float*)d_in[6];
    const float* b2  = (const float*)d_in[7];
    const float* W3  = (const float*)d_in[8];
    const float* b3  = (const float*)d_in[9];
    const float* g2  = (const float*)d_in[10];
    const float* be2 = (const float*)d_in[11];
    const float* W4  = (const float*)d_in[12];
    const float* b4  = (const float*)d_in[13];
    float* out = (float*)d_out;

    float *p_h2, *p_pooled, *p_pb, *p_sc1, *p_sh1, *p_sc2, *p_sh2;
    __nv_bfloat16 *p_yhi, *p_ylo, *p_w2hi, *p_w2lo, *p_w3hi, *p_w3lo, *p_w4hi, *p_w4lo;
    cudaGetSymbolAddress((void**)&p_h2,     g_h2);
    cudaGetSymbolAddress((void**)&p_pooled, g_pooled);
    cudaGetSymbolAddress((void**)&p_pb,     g_pb);
    cudaGetSymbolAddress((void**)&p_sc1,    g_scale1);
    cudaGetSymbolAddress((void**)&p_sh1,    g_shift1);
    cudaGetSymbolAddress((void**)&p_sc2,    g_scale2);
    cudaGetSymbolAddress((void**)&p_sh2,    g_shift2);
    cudaGetSymbolAddress((void**)&p_yhi,    g_yhi);
    cudaGetSymbolAddress((void**)&p_ylo,    g_ylo);
    cudaGetSymbolAddress((void**)&p_w2hi,   g_w2hi);
    cudaGetSymbolAddress((void**)&p_w2lo,   g_w2lo);
    cudaGetSymbolAddress((void**)&p_w3hi,   g_w3hi);
    cudaGetSymbolAddress((void**)&p_w3lo,   g_w3lo);
    cudaGetSymbolAddress((void**)&p_w4hi,   g_w4hi);
    cudaGetSymbolAddress((void**)&p_w4lo,   g_w4lo);

    // dynamic smem: 8 buffers + float block (bias/red/xs/w1/b1/sc/sh)
    const int SMEM = 8 * ABUF + (128 * 3 + 768 * 2 + 128 + 256 * 2) * 4;
    cudaFuncSetAttribute(k_tc<128,2,0>, cudaFuncAttributeMaxDynamicSharedMemorySize, SMEM);
    cudaFuncSetAttribute(k_tc<256,0,1>, cudaFuncAttributeMaxDynamicSharedMemorySize, SMEM);
    cudaFuncSetAttribute(k_tc<256,1,2>, cudaFuncAttributeMaxDynamicSharedMemorySize, SMEM);

    k_init  <<<512, 256>>>(out, p_pooled);
    k_wprep<128,256><<<256, 128>>>(W2, p_w2hi, p_w2lo);
    k_wprep<256,256><<<256, 128>>>(W3, p_w3hi, p_w3lo);
    k_wprep<256,128><<<128, 256>>>(W4, p_w4hi, p_w4lo);
    k_h_stats<<<2048, 128>>>(x, mask, W1, b1);
    k_fin1  <<<1, 128>>>(g1, be1);

    // GEMM2: y = (relu(bn1(x@W1+b1)) @ W2 + b2)*mask  [+ fused max-pool]
    k_tc<128,2,0><<<dim3(2, 2048), 256, SMEM>>>(nullptr, x, nullptr, nullptr, p_w2hi, p_w2lo,
        b2, mask, p_sc1, p_sh1, W1, b1, nullptr, p_yhi, p_ylo, p_pooled);
    k_pb    <<<512, 256>>>(W3, b3);
    // GEMM3: h2 = y @ W3[:256] + pb[batch]  [+ fused BN2 stats]
    k_tc<256,0,1><<<dim3(2, 2048), 256, SMEM>>>(nullptr, nullptr, p_yhi, p_ylo, p_w3hi, p_w3lo,
        p_pb, mask, nullptr, nullptr, nullptr, nullptr, p_h2, nullptr, nullptr, nullptr);
    k_fin2  <<<1, 256>>>(g2, be2);
    // GEMM4: out = max_n ((relu(bn2(h2)) @ W4 + b4)*mask)
    k_tc<256,1,2><<<dim3(1, 2048), 256, SMEM>>>(p_h2, nullptr, nullptr, nullptr, p_w4hi, p_w4lo,
        b4, mask, p_sc2, p_sh2, nullptr, nullptr, nullptr, nullptr, nullptr, out);
}

// round 7
// speedup vs baseline: 2.1769x; 1.0084x over previous
#include <cuda_runtime.h>
#include <cuda_bf16.h>
#include <cstdint>

#define EPS 1e-5f
#define NB  512
#define NP  512
#define MT  (NB*NP)

// ---------------- device scratch ----------------
__device__ float g_h2[(size_t)MT * 256];
__device__ __nv_bfloat16 g_yhi[(size_t)MT * 256];
__device__ __nv_bfloat16 g_ylo[(size_t)MT * 256];
__device__ __nv_bfloat16 g_w2hi[256*128], g_w2lo[256*128];
__device__ __nv_bfloat16 g_w3hi[256*256], g_w3lo[256*256];
__device__ __nv_bfloat16 g_w4hi[128*256], g_w4lo[128*256];
__device__ float g_pooled[NB*256];
__device__ float g_pb[NB*256];
__device__ float g_sum1[128], g_ss1[128];
__device__ float g_sum2[256], g_ss2[256];
__device__ float g_cnt;
__device__ float g_scale1[128], g_shift1[128];
__device__ float g_scale2[256], g_shift2[256];

// ---------------- helpers ----------------
__device__ __forceinline__ uint32_t smem_u32(const void* p) {
    uint32_t a;
    asm("{ .reg .u64 t; cvta.to.shared.u64 t, %1; cvt.u32.u64 %0, t; }" : "=r"(a) : "l"(p));
    return a;
}
__device__ __forceinline__ void ldsm4(uint32_t* r, uint32_t addr) {
    asm volatile("ldmatrix.sync.aligned.m8n8.x4.shared.b16 {%0,%1,%2,%3}, [%4];"
        : "=r"(r[0]), "=r"(r[1]), "=r"(r[2]), "=r"(r[3]) : "r"(addr));
}
__device__ __forceinline__ void mma_bf16(float* c, const uint32_t* a, uint32_t b0, uint32_t b1) {
    asm volatile(
        "mma.sync.aligned.m16n8k16.row.col.f32.bf16.bf16.f32 "
        "{%0,%1,%2,%3},{%4,%5,%6,%7},{%8,%9},{%0,%1,%2,%3};\n"
        : "+f"(c[0]), "+f"(c[1]), "+f"(c[2]), "+f"(c[3])
        : "r"(a[0]), "r"(a[1]), "r"(a[2]), "r"(a[3]), "r"(b0), "r"(b1));
}
__device__ __forceinline__ uint32_t pk(float a, float b) {
    __nv_bfloat162 t;
    t.x = __float2bfloat16(a); t.y = __float2bfloat16(b);
    return *(uint32_t*)&t;
}
__device__ __forceinline__ void cpa16(uint32_t dst, const void* src) {
    asm volatile("cp.async.cg.shared.global [%0], [%1], 16;" :: "r"(dst), "l"(src));
}
#define CPA_COMMIT() asm volatile("cp.async.commit_group;" ::: "memory")
#define CPA_WAIT0()  asm volatile("cp.async.wait_group 0;"  ::: "memory")
#define CPA_WAIT1()  asm volatile("cp.async.wait_group 1;"  ::: "memory")

// ---------------- fused prep: init + all 3 weight splits --------------------
__global__ void k_prep(float* __restrict__ out, float* __restrict__ pooled,
                       const float* __restrict__ W2, const float* __restrict__ W3,
                       const float* __restrict__ W4) {
    int i = blockIdx.x * blockDim.x + threadIdx.x;   // 512*256 = 131072
    if (i < 65536)  out[i] = 0.f;
    if (i < 131072) pooled[i] = 0.f;
    if (i < 128) { g_sum1[i] = 0.f; g_ss1[i] = 0.f; }
    if (i < 256) { g_sum2[i] = 0.f; g_ss2[i] = 0.f; }
    if (i == 0)  g_cnt = 0.f;
    if (i < 32768) {                  // W2: [128 k][256 n] -> [n][128]
        int k = i >> 8, n = i & 255;
        float v = W2[k * 256 + n];
        __nv_bfloat16 h = __float2bfloat16(v);
        g_w2hi[n * 128 + k] = h;
        g_w2lo[n * 128 + k] = __float2bfloat16(v - __bfloat162float(h));
    }
    if (i < 65536) {                  // W3: [256 k][256 n] -> [n][256]
        int k = i >> 8, n = i & 255;
        float v = W3[k * 256 + n];
        __nv_bfloat16 h = __float2bfloat16(v);
        g_w3hi[n * 256 + k] = h;
        g_w3lo[n * 256 + k] = __float2bfloat16(v - __bfloat162float(h));
    }
    if (i < 32768) {                  // W4: [256 k][128 n] -> [n][256]
        int k = i >> 7, n = i & 127;
        float v = W4[k * 128 + n];
        __nv_bfloat16 h = __float2bfloat16(v);
        g_w4hi[n * 256 + k] = h;
        g_w4lo[n * 256 + k] = __float2bfloat16(v - __bfloat162float(h));
    }
}

// masked stats over h = x@W1+b1 (h never stored)
__global__ void k_h_stats(const float* __restrict__ x, const int* __restrict__ mask,
                          const float* __restrict__ W1, const float* __restrict__ b1) {
    int c  = threadIdx.x;
    int p0 = blockIdx.x * 128;
    __shared__ float xs[128 * 6];
    __shared__ int   ms[128];
    for (int idx = c; idx < 768; idx += 128) xs[idx] = x[p0 * 6 + idx];
    ms[c] = mask[p0 + c];
    __syncthreads();
    float w0 = W1[0*128+c], w1 = W1[1*128+c], w2 = W1[2*128+c];
    float w3 = W1[3*128+c], w4 = W1[4*128+c], w5 = W1[5*128+c];
    float bb = b1[c];
    float s = 0.f, ss = 0.f; int cnt = 0;
    for (int i = 0; i < 128; i++) {
        if (!ms[i]) continue;
        const float* xp = &xs[i * 6];
        float t = bb + xp[0]*w0 + xp[1]*w1 + xp[2]*w2 + xp[3]*w3 + xp[4]*w4 + xp[5]*w5;
        s += t; ss += t * t; cnt++;
    }
    atomicAdd(&g_sum1[c], s);
    atomicAdd(&g_ss1[c],  ss);
    if (c == 0) atomicAdd(&g_cnt, (float)cnt);
}

__global__ void k_fin1(const float* __restrict__ g1, const float* __restrict__ be1) {
    int c = threadIdx.x;
    float cnt  = g_cnt;
    float mean = g_sum1[c] / cnt;
    float var  = g_ss1[c] / cnt - mean * mean;
    float sc   = g1[c] * rsqrtf(var + EPS);
    g_scale1[c] = sc; g_shift1[c] = be1[c] - mean * sc;
}
__global__ void k_fin2(const float* __restrict__ g2, const float* __restrict__ be2) {
    int c = threadIdx.x;
    float cnt  = g_cnt;
    float mean = g_sum2[c] / cnt;
    float var  = g_ss2[c] / cnt - mean * mean;
    float sc   = g2[c] * rsqrtf(var + EPS);
    g_scale2[c] = sc; g_shift2[c] = be2[c] - mean * sc;
}

__global__ void k_pb(const float* __restrict__ W3, const float* __restrict__ b3) {
    int b = blockIdx.x, j = threadIdx.x;
    __shared__ float pl[256];
    pl[j] = g_pooled[b * 256 + j];
    __syncthreads();
    float s = b3[j];
#pragma unroll 4
    for (int k = 0; k < 256; k++) s += pl[k] * W3[(256 + k) * 256 + j];
    g_pb[b * 256 + j] = s;
}

// ---------------- pipelined tensor GEMM, tile 128x128, BK=32, 256 thr, 2 CTA/SM
// AMODE: 0 = A pre-split bf16 hi/lo via cp.async (TRIPLE-buffered, depth-2 lookahead)
//        1 = A fp32 LDG + relu(a*sc+sh) + split (register prefetch)
//        2 = A computed from x@W1+b1 then relu(bn1) (no A gmem traffic)
// EMODE: 0 = y: (+bias)*mask, store split bf16, fused max-pool
//        1 = h2: +bias[batch*256+col], store fp32, fused masked stats
//        2 = out: (+bias)*mask, max over rows -> redT[batch*128+col]
#define ABUF 10240     // bytes: 128 rows x 40 cols x 2B (one half, one buffer)

template<int KTOT, int AMODE, int EMODE>
__global__ void __launch_bounds__(256, 2) k_tc(
    const float* __restrict__ Af, const float* __restrict__ xin,
    const __nv_bfloat16* __restrict__ Ahi, const __nv_bfloat16* __restrict__ Alo,
    const __nv_bfloat16* __restrict__ Bhi, const __nv_bfloat16* __restrict__ Blo,
    const float* __restrict__ bias, const int* __restrict__ maskp,
    const float* __restrict__ scA, const float* __restrict__ shA,
    const float* __restrict__ W1, const float* __restrict__ b1,
    float* __restrict__ Cf,
    __nv_bfloat16* __restrict__ Chi, __nv_bfloat16* __restrict__ Clo,
    float* __restrict__ redT)
{
    constexpr int C = KTOT / 32;
    constexpr int ADEPTH = (AMODE == 0) ? 3 : 2;
    constexpr int FBOFF  = (2 * ADEPTH + 4) * ABUF;

    extern __shared__ __align__(128) char sm[];
    const uint32_t sb = smem_u32(sm);
    // A hi buf i: sb + i*ABUF ; A lo buf i: sb + (ADEPTH+i)*ABUF
    // B hi buf j: sb + (2*ADEPTH+j)*ABUF ; B lo buf j: +2 more
    float* fb     = (float*)(sm + FBOFF);
    float* bias_s = fb;                      // [128]
    float* redA   = fb + 128;                // [128]
    float* redB   = fb + 256;                // [128]
    int*   pool_s = (int*)redA;
    float* scs    = fb + 384;                // [256]  (AMODE>=1)
    float* shs    = scs + 256;               // [256]
    float* xs     = shs + 256;               // [768]  (AMODE==2)
    float* w1s    = xs + 768;                // [768]
    float* b1s    = w1s + 768;               // [128]

    const int tid  = threadIdx.x;
    const int wid  = tid >> 5;
    const int lane = tid & 31;
    const int warp_m = wid & 3;
    const int warp_n = wid >> 2;
    const int g  = lane >> 2, t4 = lane & 3;
    const int colBase = blockIdx.x * 128;
    const int rowBase = blockIdx.y * 128;
    const int batch   = rowBase >> 9;

    if (AMODE >= 1) {
        for (int i = tid; i < KTOT; i += 256) { scs[i] = scA[i]; shs[i] = shA[i]; }
    }
    if (AMODE == 2) {
        for (int i = tid; i < 768; i += 256) {
            xs[i]  = xin[(size_t)rowBase * 6 + i];
            w1s[i] = W1[i];
        }
        if (tid < 128) b1s[tid] = b1[tid];
    }
    if (tid < 128) bias_s[tid] = bias[(EMODE == 1 ? batch * 256 : 0) + colBase + tid];
    __syncthreads();

    float acc[2][8][4];
#pragma unroll
    for (int i = 0; i < 2; i++)
#pragma unroll
        for (int j = 0; j < 8; j++)
#pragma unroll
            for (int l = 0; l < 4; l++) acc[i][j][l] = 0.f;

    const int lrow = lane & 7, lsel = lane >> 3;
    const int aRowOff = (lsel & 1) * 8 + lrow, aKOff = (lsel >> 1) * 8;
    const int bRowOff = (lsel >> 1) * 8 + lrow, bKOff = (lsel & 1) * 8;

    auto stageA_async = [&](int k0, int buf) {   // AMODE==0
#pragma unroll
        for (int i = 0; i < 2; i++) {
            int idx = tid + i * 256;
            int row = idx >> 2, k8 = (idx & 3) * 8;
            uint32_t so = (uint32_t)(row * 40 + k8) * 2;
            size_t go = (size_t)(rowBase + row) * KTOT + k0 + k8;
            cpa16(sb + buf * ABUF + so,            Ahi + go);
            cpa16(sb + (ADEPTH + buf) * ABUF + so, Alo + go);
        }
    };
    auto stageA_compute = [&](int k0, int buf) { // AMODE==2
#pragma unroll
        for (int i = 0; i < 2; i++) {
            int idx = tid + i * 256;
            int row = idx >> 2, k8 = (idx & 3) * 8;
            float xr[6];
#pragma unroll
            for (int d = 0; d < 6; d++) xr[d] = xs[row * 6 + d];
            uint32_t H[4], L[4];
#pragma unroll
            for (int jp = 0; jp < 4; jp++) {
                float tv[2];
#pragma unroll
                for (int q = 0; q < 2; q++) {
                    int kk = k0 + k8 + jp * 2 + q;
                    float t = b1s[kk];
#pragma unroll
                    for (int d = 0; d < 6; d++) t += xr[d] * w1s[d * 128 + kk];
                    tv[q] = fmaxf(t * scs[kk] + shs[kk], 0.f);
                }
                float h0 = __bfloat162float(__float2bfloat16(tv[0]));
                float h1 = __bfloat162float(__float2bfloat16(tv[1]));
                H[jp] = pk(tv[0], tv[1]);
                L[jp] = pk(tv[0] - h0, tv[1] - h1);
            }
            uint32_t so = (uint32_t)(row * 40 + k8) * 2;
            *(uint4*)(sm + buf * ABUF + so)            = make_uint4(H[0], H[1], H[2], H[3]);
            *(uint4*)(sm + (ADEPTH + buf) * ABUF + so) = make_uint4(L[0], L[1], L[2], L[3]);
        }
    };
    auto stageB = [&](int k0, int buf) {
#pragma unroll
        for (int i = 0; i < 2; i++) {
            int idx = tid + i * 256;
            int row = idx >> 2, k8 = (idx & 3) * 8;
            uint32_t so = (uint32_t)(row * 40 + k8) * 2;
            size_t go = (size_t)(colBase + row) * KTOT + k0 + k8;
            cpa16(sb + (2 * ADEPTH + buf) * ABUF + so,     Bhi + go);
            cpa16(sb + (2 * ADEPTH + 2 + buf) * ABUF + so, Blo + go);
        }
    };

    // AMODE==1: register prefetch of A fp32
    float pf[AMODE == 1 ? 16 : 1];
    const int ldRow1 = tid >> 1, ldKh1 = (tid & 1) * 16;
    auto ldgA1 = [&](int k0) {
        const float* ap = Af + (size_t)(rowBase + ldRow1) * KTOT + k0 + ldKh1;
#pragma unroll
        for (int q = 0; q < 4; q++) {
            float4 v = *(const float4*)(ap + q * 4);
            pf[q*4+0] = v.x; pf[q*4+1] = v.y; pf[q*4+2] = v.z; pf[q*4+3] = v.w;
        }
    };
    auto stsA1 = [&](int k0, int buf) {
        uint32_t H[8], L[8];
#pragma unroll
        for (int jp = 0; jp < 8; jp++) {
            float t0 = fmaxf(pf[jp*2]   * scs[k0 + ldKh1 + jp*2]   + shs[k0 + ldKh1 + jp*2],   0.f);
            float t1 = fmaxf(pf[jp*2+1] * scs[k0 + ldKh1 + jp*2+1] + shs[k0 + ldKh1 + jp*2+1], 0.f);
            float h0 = __bfloat162float(__float2bfloat16(t0));
            float h1 = __bfloat162float(__float2bfloat16(t1));
            H[jp] = pk(t0, t1);
            L[jp] = pk(t0 - h0, t1 - h1);
        }
        uint32_t so = (uint32_t)(ldRow1 * 40 + ldKh1) * 2;
        *(uint4*)(sm + buf * ABUF + so)                 = make_uint4(H[0], H[1], H[2], H[3]);
        *(uint4*)(sm + buf * ABUF + so + 16)            = make_uint4(H[4], H[5], H[6], H[7]);
        *(uint4*)(sm + (ADEPTH + buf) * ABUF + so)      = make_uint4(L[0], L[1], L[2], L[3]);
        *(uint4*)(sm + (ADEPTH + buf) * ABUF + so + 16) = make_uint4(L[4], L[5], L[6], L[7]);
    };

    auto mma_chunk = [&](int abuf, int bbuf) {
#pragma unroll
        for (int kk = 0; kk < 32; kk += 16) {
            uint32_t ah[2][4], al[2][4];
#pragma unroll
            for (int mt = 0; mt < 2; mt++) {
                int ar = warp_m * 32 + mt * 16;
                uint32_t off = (uint32_t)((ar + aRowOff) * 40 + kk + aKOff) * 2;
                ldsm4(ah[mt], sb + abuf * ABUF + off);
                ldsm4(al[mt], sb + (ADEPTH + abuf) * ABUF + off);
            }
#pragma unroll
            for (int ng = 0; ng < 4; ng++) {
                int bn = warp_n * 64 + ng * 16;
                uint32_t off = (uint32_t)((bn + bRowOff) * 40 + kk + bKOff) * 2;
                uint32_t bh[4], bl[4];
                ldsm4(bh, sb + (2 * ADEPTH + bbuf) * ABUF + off);
                ldsm4(bl, sb + (2 * ADEPTH + 2 + bbuf) * ABUF + off);
#pragma unroll
                for (int hf = 0; hf < 2; hf++) {
                    int nt = ng * 2 + hf;
                    uint32_t b0 = bh[hf * 2], b1r = bh[hf * 2 + 1];
                    uint32_t c0 = bl[hf * 2], c1r = bl[hf * 2 + 1];
#pragma unroll
                    for (int mt = 0; mt < 2; mt++) {
                        mma_bf16(acc[mt][nt], ah[mt], b0, b1r);
                        mma_bf16(acc[mt][nt], ah[mt], c0, c1r);
                        mma_bf16(acc[mt][nt], al[mt], b0, b1r);
                    }
                }
            }
        }
    };

    if (AMODE == 0) {
        // ---- triple-buffered A (depth 2), double-buffered B (depth 1) ----
        stageA_async(0, 0); stageB(0, 0); CPA_COMMIT();
        stageA_async(32, 1); CPA_COMMIT();
        CPA_WAIT1(); __syncthreads();
        for (int c = 0; c < C; c++) {
            if (c + 1 < C) stageB((c + 1) * 32, (c + 1) & 1);
            CPA_COMMIT();
            if (c + 2 < C) stageA_async((c + 2) * 32, (c + 2) % 3);
            CPA_COMMIT();
            mma_chunk(c % 3, c & 1);
            CPA_WAIT1(); __syncthreads();
        }
    } else {
        // ---- double-buffered ----
        if (AMODE == 2) stageA_compute(0, 0);
        else          { ldgA1(0); stsA1(0, 0); }
        stageB(0, 0);
        CPA_COMMIT();
        CPA_WAIT0();
        __syncthreads();
        for (int c = 0; c < C; c++) {
            const int buf = c & 1;
            if (c + 1 < C) {
                const int k0n = (c + 1) * 32;
                if (AMODE == 2) stageA_compute(k0n, buf ^ 1);
                else            ldgA1(k0n);
                stageB(k0n, buf ^ 1);
                CPA_COMMIT();
            }
            mma_chunk(buf, buf);
            if (AMODE == 1 && c + 1 < C) stsA1((c + 1) * 32, buf ^ 1);
            CPA_WAIT0();
            __syncthreads();
        }
    }

    // ---------------- epilogue ----------------
    if (tid < 128) { pool_s[tid] = 0; redA[tid] = 0.f; redB[tid] = 0.f; }
    __syncthreads();

    if (EMODE == 0) {
#pragma unroll
        for (int mt = 0; mt < 2; mt++) {
            int r0 = rowBase + warp_m * 32 + mt * 16 + g;
            int r1 = r0 + 8;
            float m0 = (maskp[r0] != 0) ? 1.f : 0.f;
            float m1 = (maskp[r1] != 0) ? 1.f : 0.f;
#pragma unroll
            for (int nt = 0; nt < 8; nt++) {
                int lc = warp_n * 64 + nt * 8 + 2 * t4;
                int c0 = colBase + lc;
                float bx = bias_s[lc], by = bias_s[lc + 1];
                float v00 = (acc[mt][nt][0] + bx) * m0;
                float v01 = (acc[mt][nt][1] + by) * m0;
                float v10 = (acc[mt][nt][2] + bx) * m1;
                float v11 = (acc[mt][nt][3] + by) * m1;
                float h00 = __bfloat162float(__float2bfloat16(v00));
                float h01 = __bfloat162float(__float2bfloat16(v01));
                float h10 = __bfloat162float(__float2bfloat16(v10));
                float h11 = __bfloat162float(__float2bfloat16(v11));
                *(uint32_t*)&Chi[(size_t)r0 * 256 + c0] = pk(v00, v01);
                *(uint32_t*)&Chi[(size_t)r1 * 256 + c0] = pk(v10, v11);
                *(uint32_t*)&Clo[(size_t)r0 * 256 + c0] = pk(v00 - h00, v01 - h01);
                *(uint32_t*)&Clo[(size_t)r1 * 256 + c0] = pk(v10 - h10, v11 - h11);
                float p0 = fmaxf(v00, v10), p1 = fmaxf(v01, v11);
                if (p0 > 0.f) atomicMax(&pool_s[lc],     __float_as_int(p0));
                if (p1 > 0.f) atomicMax(&pool_s[lc + 1], __float_as_int(p1));
            }
        }
        __syncthreads();
        if (tid < 128) {
            int v = pool_s[tid];
            if (v > 0) atomicMax((int*)&redT[batch * 256 + colBase + tid], v);
        }
    } else if (EMODE == 1) {
#pragma unroll
        for (int nt = 0; nt < 8; nt++) {
            int lc = warp_n * 64 + nt * 8 + 2 * t4;
            int c0 = colBase + lc;
            float bx = bias_s[lc], by = bias_s[lc + 1];
            float s0 = 0.f, s1 = 0.f, q0 = 0.f, q1 = 0.f;
#pragma unroll
            for (int mt = 0; mt < 2; mt++) {
                int r0 = rowBase + warp_m * 32 + mt * 16 + g;
                int r1 = r0 + 8;
                float v00 = acc[mt][nt][0] + bx;
                float v01 = acc[mt][nt][1] + by;
                float v10 = acc[mt][nt][2] + bx;
                float v11 = acc[mt][nt][3] + by;
                *(float2*)&Cf[(size_t)r0 * 256 + c0] = make_float2(v00, v01);
                *(float2*)&Cf[(size_t)r1 * 256 + c0] = make_float2(v10, v11);
                if (maskp[r0]) { s0 += v00; s1 += v01; q0 += v00*v00; q1 += v01*v01; }
                if (maskp[r1]) { s0 += v10; s1 += v11; q0 += v10*v10; q1 += v11*v11; }
            }
            atomicAdd(&redA[lc],     s0);
            atomicAdd(&redA[lc + 1], s1);
            atomicAdd(&redB[lc],     q0);
            atomicAdd(&redB[lc + 1], q1);
        }
        __syncthreads();
        if (tid < 128) {
            atomicAdd(&g_sum2[colBase + tid], redA[tid]);
            atomicAdd(&g_ss2[colBase + tid],  redB[tid]);
        }
    } else {
#pragma unroll
        for (int nt = 0; nt < 8; nt++) {
            int lc = warp_n * 64 + nt * 8 + 2 * t4;
            float bx = bias_s[lc], by = bias_s[lc + 1];
            float p0 = 0.f, p1 = 0.f;
#pragma unroll
            for (int mt = 0; mt < 2; mt++) {
                int r0 = rowBase + warp_m * 32 + mt * 16 + g;
                int r1 = r0 + 8;
                float m0 = (maskp[r0] != 0) ? 1.f : 0.f;
                float m1 = (maskp[r1] != 0) ? 1.f : 0.f;
                p0 = fmaxf(p0, (acc[mt][nt][0] + bx) * m0);
                p1 = fmaxf(p1, (acc[mt][nt][1] + by) * m0);
                p0 = fmaxf(p0, (acc[mt][nt][2] + bx) * m1);
                p1 = fmaxf(p1, (acc[mt][nt][3] + by) * m1);
            }
            if (p0 > 0.f) atomicMax(&pool_s[lc],     __float_as_int(p0));
            if (p1 > 0.f) atomicMax(&pool_s[lc + 1], __float_as_int(p1));
        }
        __syncthreads();
        if (tid < 128) {
            int v = pool_s[tid];
            if (v > 0) atomicMax((int*)&redT[batch * 128 + tid], v);
        }
    }
}

// ---------------- launch ----------------
extern "C" void kernel_launch(void* const* d_in, const int* in_sizes, int n_in,
                              void* d_out, int out_size) {
    const float* x   = (const float*)d_in[0];
    const int*   mask= (const int*)  d_in[1];
    const float* W1  = (const float*)d_in[2];
    const float* b1  = (const float*)d_in[3];
    const float* g1  = (const float*)d_in[4];
    const float* be1 = (const float*)d_in[5];
    const float* W2  = (const float*)d_in[6];
    const float* b2  = (const float*)d_in[7];
    const float* W3  = (const float*)d_in[8];
    const float* b3  = (const float*)d_in[9];
    const float* g2  = (const float*)d_in[10];
    const float* be2 = (const float*)d_in[11];
    const float* W4  = (const float*)d_in[12];
    const float* b4  = (const float*)d_in[13];
    float* out = (float*)d_out;

    float *p_h2, *p_pooled, *p_pb, *p_sc1, *p_sh1, *p_sc2, *p_sh2;
    __nv_bfloat16 *p_yhi, *p_ylo, *p_w2hi, *p_w2lo, *p_w3hi, *p_w3lo, *p_w4hi, *p_w4lo;
    cudaGetSymbolAddress((void**)&p_h2,     g_h2);
    cudaGetSymbolAddress((void**)&p_pooled, g_pooled);
    cudaGetSymbolAddress((void**)&p_pb,     g_pb);
    cudaGetSymbolAddress((void**)&p_sc1,    g_scale1);
    cudaGetSymbolAddress((void**)&p_sh1,    g_shift1);
    cudaGetSymbolAddress((void**)&p_sc2,    g_scale2);
    cudaGetSymbolAddress((void**)&p_sh2,    g_shift2);
    cudaGetSymbolAddress((void**)&p_yhi,    g_yhi);
    cudaGetSymbolAddress((void**)&p_ylo,    g_ylo);
    cudaGetSymbolAddress((void**)&p_w2hi,   g_w2hi);
    cudaGetSymbolAddress((void**)&p_w2lo,   g_w2lo);
    cudaGetSymbolAddress((void**)&p_w3hi,   g_w3hi);
    cudaGetSymbolAddress((void**)&p_w3lo,   g_w3lo);
    cudaGetSymbolAddress((void**)&p_w4hi,   g_w4hi);
    cudaGetSymbolAddress((void**)&p_w4lo,   g_w4lo);

    // per-kernel dynamic smem
    const int SM_G2 = 8  * ABUF + (128*3 + 256*2 + 768*2 + 128) * 4;  // AMODE2: full extras
    const int SM_G3 = 10 * ABUF + (128*3) * 4;                        // AMODE0: minimal
    const int SM_G4 = 8  * ABUF + (128*3 + 256*2) * 4;                // AMODE1: +sc/sh
    cudaFuncSetAttribute(k_tc<128,2,0>, cudaFuncAttributeMaxDynamicSharedMemorySize, SM_G2);
    cudaFuncSetAttribute(k_tc<256,0,1>, cudaFuncAttributeMaxDynamicSharedMemorySize, SM_G3);
    cudaFuncSetAttribute(k_tc<256,1,2>, cudaFuncAttributeMaxDynamicSharedMemorySize, SM_G4);

    k_prep   <<<512, 256>>>(out, p_pooled, W2, W3, W4);
    k_h_stats<<<2048, 128>>>(x, mask, W1, b1);
    k_fin1   <<<1, 128>>>(g1, be1);

    // GEMM2 (4th launch -> ncu target): y = (relu(bn1(x@W1+b1)) @ W2 + b2)*mask [+ max-pool]
    k_tc<128,2,0><<<dim3(2, 2048), 256, SM_G2>>>(nullptr, x, nullptr, nullptr, p_w2hi, p_w2lo,
        b2, mask, p_sc1, p_sh1, W1, b1, nullptr, p_yhi, p_ylo, p_pooled);
    k_pb     <<<512, 256>>>(W3, b3);
    // GEMM3: h2 = y @ W3[:256] + pb[batch]  [+ fused BN2 stats]  (triple-buffered A)
    k_tc<256,0,1><<<dim3(2, 2048), 256, SM_G3>>>(nullptr, nullptr, p_yhi, p_ylo, p_w3hi, p_w3lo,
        p_pb, mask, nullptr, nullptr, nullptr, nullptr, p_h2, nullptr, nullptr, nullptr);
    k_fin2   <<<1, 256>>>(g2, be2);
    // GEMM4: out = max_n ((relu(bn2(h2)) @ W4 + b4)*mask)
    k_tc<256,1,2><<<dim3(1, 2048), 256, SM_G4>>>(p_h2, nullptr, nullptr, nullptr, p_w4hi, p_w4lo,
        b4, mask, p_sc2, p_sh2, nullptr, nullptr, nullptr, nullptr, nullptr, out);
}

// round 8
// speedup vs baseline: 2.2141x; 1.0171x over previous
#include <cuda_runtime.h>
#include <cuda_bf16.h>
#include <cstdint>

#define EPS 1e-5f
#define NB  512
#define NP  512
#define MT  (NB*NP)

// ---------------- device scratch ----------------
__device__ float g_h2[(size_t)MT * 256];
__device__ __nv_bfloat16 g_yhi[(size_t)MT * 256];
__device__ __nv_bfloat16 g_ylo[(size_t)MT * 256];
__device__ __nv_bfloat16 g_w2hi[256*128], g_w2lo[256*128];
__device__ __nv_bfloat16 g_w3hi[256*256], g_w3lo[256*256];
__device__ __nv_bfloat16 g_w4hi[128*256], g_w4lo[128*256];
__device__ float g_pooled[NB*256];
__device__ float g_pb[NB*256];
__device__ float g_sum1[128], g_ss1[128];
__device__ float g_sum2[256], g_ss2[256];
__device__ float g_cnt;
__device__ float g_scale1[128], g_shift1[128];
__device__ float g_scale2[256], g_shift2[256];

// ---------------- helpers ----------------
__device__ __forceinline__ uint32_t smem_u32(const void* p) {
    uint32_t a;
    asm("{ .reg .u64 t; cvta.to.shared.u64 t, %1; cvt.u32.u64 %0, t; }" : "=r"(a) : "l"(p));
    return a;
}
__device__ __forceinline__ void ldsm4(uint32_t* r, uint32_t addr) {
    asm volatile("ldmatrix.sync.aligned.m8n8.x4.shared.b16 {%0,%1,%2,%3}, [%4];"
        : "=r"(r[0]), "=r"(r[1]), "=r"(r[2]), "=r"(r[3]) : "r"(addr));
}
__device__ __forceinline__ void mma_bf16(float* c, const uint32_t* a, uint32_t b0, uint32_t b1) {
    asm volatile(
        "mma.sync.aligned.m16n8k16.row.col.f32.bf16.bf16.f32 "
        "{%0,%1,%2,%3},{%4,%5,%6,%7},{%8,%9},{%0,%1,%2,%3};\n"
        : "+f"(c[0]), "+f"(c[1]), "+f"(c[2]), "+f"(c[3])
        : "r"(a[0]), "r"(a[1]), "r"(a[2]), "r"(a[3]), "r"(b0), "r"(b1));
}
__device__ __forceinline__ uint32_t pk(float a, float b) {
    __nv_bfloat162 t;
    t.x = __float2bfloat16(a); t.y = __float2bfloat16(b);
    return *(uint32_t*)&t;
}
__device__ __forceinline__ void cpa16(uint32_t dst, const void* src) {
    asm volatile("cp.async.cg.shared.global [%0], [%1], 16;" :: "r"(dst), "l"(src));
}
#define CPA_COMMIT() asm volatile("cp.async.commit_group;" ::: "memory")
#define CPA_WAIT0()  asm volatile("cp.async.wait_group 0;"  ::: "memory")
#define CPA_WAIT1()  asm volatile("cp.async.wait_group 1;"  ::: "memory")

// ---------------- fused prep: init + all 3 weight splits --------------------
__global__ void k_prep(float* __restrict__ out, float* __restrict__ pooled,
                       const float* __restrict__ W2, const float* __restrict__ W3,
                       const float* __restrict__ W4) {
    int i = blockIdx.x * blockDim.x + threadIdx.x;
    if (i < 65536)  out[i] = 0.f;
    if (i < 131072) pooled[i] = 0.f;
    if (i < 128) { g_sum1[i] = 0.f; g_ss1[i] = 0.f; }
    if (i < 256) { g_sum2[i] = 0.f; g_ss2[i] = 0.f; }
    if (i == 0)  g_cnt = 0.f;
    if (i < 32768) {
        int k = i >> 8, n = i & 255;
        float v = W2[k * 256 + n];
        __nv_bfloat16 h = __float2bfloat16(v);
        g_w2hi[n * 128 + k] = h;
        g_w2lo[n * 128 + k] = __float2bfloat16(v - __bfloat162float(h));
    }
    if (i < 65536) {
        int k = i >> 8, n = i & 255;
        float v = W3[k * 256 + n];
        __nv_bfloat16 h = __float2bfloat16(v);
        g_w3hi[n * 256 + k] = h;
        g_w3lo[n * 256 + k] = __float2bfloat16(v - __bfloat162float(h));
    }
    if (i < 32768) {
        int k = i >> 7, n = i & 127;
        float v = W4[k * 128 + n];
        __nv_bfloat16 h = __float2bfloat16(v);
        g_w4hi[n * 256 + k] = h;
        g_w4lo[n * 256 + k] = __float2bfloat16(v - __bfloat162float(h));
    }
}

// masked stats over h = x@W1+b1 (h never stored)
__global__ void k_h_stats(const float* __restrict__ x, const int* __restrict__ mask,
                          const float* __restrict__ W1, const float* __restrict__ b1) {
    int c  = threadIdx.x;
    int p0 = blockIdx.x * 128;
    __shared__ float xs[128 * 6];
    __shared__ int   ms[128];
    for (int idx = c; idx < 768; idx += 128) xs[idx] = x[p0 * 6 + idx];
    ms[c] = mask[p0 + c];
    __syncthreads();
    float w0 = W1[0*128+c], w1 = W1[1*128+c], w2 = W1[2*128+c];
    float w3 = W1[3*128+c], w4 = W1[4*128+c], w5 = W1[5*128+c];
    float bb = b1[c];
    float s = 0.f, ss = 0.f; int cnt = 0;
    for (int i = 0; i < 128; i++) {
        if (!ms[i]) continue;
        const float* xp = &xs[i * 6];
        float t = bb + xp[0]*w0 + xp[1]*w1 + xp[2]*w2 + xp[3]*w3 + xp[4]*w4 + xp[5]*w5;
        s += t; ss += t * t; cnt++;
    }
    atomicAdd(&g_sum1[c], s);
    atomicAdd(&g_ss1[c],  ss);
    if (c == 0) atomicAdd(&g_cnt, (float)cnt);
}

__global__ void k_fin1(const float* __restrict__ g1, const float* __restrict__ be1) {
    int c = threadIdx.x;
    float cnt  = g_cnt;
    float mean = g_sum1[c] / cnt;
    float var  = g_ss1[c] / cnt - mean * mean;
    float sc   = g1[c] * rsqrtf(var + EPS);
    g_scale1[c] = sc; g_shift1[c] = be1[c] - mean * sc;
}
__global__ void k_fin2(const float* __restrict__ g2, const float* __restrict__ be2) {
    int c = threadIdx.x;
    float cnt  = g_cnt;
    float mean = g_sum2[c] / cnt;
    float var  = g_ss2[c] / cnt - mean * mean;
    float sc   = g2[c] * rsqrtf(var + EPS);
    g_scale2[c] = sc; g_shift2[c] = be2[c] - mean * sc;
}

__global__ void k_pb(const float* __restrict__ W3, const float* __restrict__ b3) {
    int b = blockIdx.x, j = threadIdx.x;
    __shared__ float pl[256];
    pl[j] = g_pooled[b * 256 + j];
    __syncthreads();
    float s = b3[j];
#pragma unroll 4
    for (int k = 0; k < 256; k++) s += pl[k] * W3[(256 + k) * 256 + j];
    g_pb[b * 256 + j] = s;
}

// ---------------- pipelined tensor GEMM, tile 128x128, BK=32, 256 thr, 2 CTA/SM
// AMODE: 0 = A pre-split bf16 hi/lo via cp.async (triple-buffered)
//        1 = A fp32 LDG + relu(a*sc+sh) + split (vectorized sc/sh)
//        2 = A computed from x@W1p+b1p (BN folded into weights), relu, split
// EMODE: 0 = y: (+bias)*mask, store split bf16, fused max-pool
//        1 = h2: +bias[batch*256+col], store fp32, fused masked stats
//        2 = out: (+bias)*mask, max over rows -> redT[batch*128+col]
#define ABUF 10240

template<int KTOT, int AMODE, int EMODE>
__global__ void __launch_bounds__(256, 2) k_tc(
    const float* __restrict__ Af, const float* __restrict__ xin,
    const __nv_bfloat16* __restrict__ Ahi, const __nv_bfloat16* __restrict__ Alo,
    const __nv_bfloat16* __restrict__ Bhi, const __nv_bfloat16* __restrict__ Blo,
    const float* __restrict__ bias, const int* __restrict__ maskp,
    const float* __restrict__ scA, const float* __restrict__ shA,
    const float* __restrict__ W1, const float* __restrict__ b1,
    float* __restrict__ Cf,
    __nv_bfloat16* __restrict__ Chi, __nv_bfloat16* __restrict__ Clo,
    float* __restrict__ redT)
{
    constexpr int C = KTOT / 32;
    constexpr int ADEPTH = (AMODE == 0) ? 3 : 2;
    constexpr int FBOFF  = (2 * ADEPTH + 4) * ABUF;

    extern __shared__ __align__(128) char sm[];
    const uint32_t sb = smem_u32(sm);
    float* fb     = (float*)(sm + FBOFF);
    float* bias_s = fb;                      // [128]
    float* redA   = fb + 128;                // [128]
    float* redB   = fb + 256;                // [128]
    int*   pool_s = (int*)redA;
    float* scs    = fb + 384;                // [256]  (AMODE==1)
    float* shs    = scs + 256;               // [256]
    float* w1s    = shs + 256;               // [768]  (AMODE==2: W1*sc folded)
    float* b1s    = w1s + 768;               // [128]  (AMODE==2: b1*sc+sh folded)

    const int tid  = threadIdx.x;
    const int wid  = tid >> 5;
    const int lane = tid & 31;
    const int warp_m = wid & 3;
    const int warp_n = wid >> 2;
    const int g  = lane >> 2, t4 = lane & 3;
    const int colBase = blockIdx.x * 128;
    const int rowBase = blockIdx.y * 128;
    const int batch   = rowBase >> 9;

    if (AMODE == 1) {
        for (int i = tid; i < KTOT; i += 256) { scs[i] = scA[i]; shs[i] = shA[i]; }
    }
    if (AMODE == 2) {
        // fold BN into weights: w1p = W1*sc[k], b1p = b1*sc[k]+sh[k]
        for (int i = tid; i < 768; i += 256) w1s[i] = W1[i] * scA[i & 127];
        if (tid < 128) b1s[tid] = b1[tid] * scA[tid] + shA[tid];
    }
    if (tid < 128) bias_s[tid] = bias[(EMODE == 1 ? batch * 256 : 0) + colBase + tid];
    __syncthreads();

    // hoist per-thread x rows into registers (rows fixed across chunks)
    float xr[2][6];
    if (AMODE == 2) {
#pragma unroll
        for (int i = 0; i < 2; i++) {
            int row = (tid + i * 256) >> 2;
            const float* xp = xin + (size_t)(rowBase + row) * 6;
            float2 a = *(const float2*)xp;
            float2 b = *(const float2*)(xp + 2);
            float2 cc = *(const float2*)(xp + 4);
            xr[i][0] = a.x; xr[i][1] = a.y; xr[i][2] = b.x;
            xr[i][3] = b.y; xr[i][4] = cc.x; xr[i][5] = cc.y;
        }
    }

    float acc[2][8][4];
#pragma unroll
    for (int i = 0; i < 2; i++)
#pragma unroll
        for (int j = 0; j < 8; j++)
#pragma unroll
            for (int l = 0; l < 4; l++) acc[i][j][l] = 0.f;

    const int lrow = lane & 7, lsel = lane >> 3;
    const int aRowOff = (lsel & 1) * 8 + lrow, aKOff = (lsel >> 1) * 8;
    const int bRowOff = (lsel >> 1) * 8 + lrow, bKOff = (lsel & 1) * 8;

    auto stageA_async = [&](int k0, int buf) {   // AMODE==0
#pragma unroll
        for (int i = 0; i < 2; i++) {
            int idx = tid + i * 256;
            int row = idx >> 2, k8 = (idx & 3) * 8;
            uint32_t so = (uint32_t)(row * 40 + k8) * 2;
            size_t go = (size_t)(rowBase + row) * KTOT + k0 + k8;
            cpa16(sb + buf * ABUF + so,            Ahi + go);
            cpa16(sb + (ADEPTH + buf) * ABUF + so, Alo + go);
        }
    };
    auto stageA_compute = [&](int k0, int buf) { // AMODE==2, vectorized
#pragma unroll
        for (int i = 0; i < 2; i++) {
            int idx = tid + i * 256;
            int row = idx >> 2, k8 = (idx & 3) * 8;
            int kb = k0 + k8;
            float4 a0 = *(const float4*)&b1s[kb];
            float4 a1 = *(const float4*)&b1s[kb + 4];
#pragma unroll
            for (int d = 0; d < 6; d++) {
                float xv = xr[i][d];
                float4 w0 = *(const float4*)&w1s[d * 128 + kb];
                float4 w1v = *(const float4*)&w1s[d * 128 + kb + 4];
                a0.x += xv * w0.x;  a0.y += xv * w0.y;
                a0.z += xv * w0.z;  a0.w += xv * w0.w;
                a1.x += xv * w1v.x; a1.y += xv * w1v.y;
                a1.z += xv * w1v.z; a1.w += xv * w1v.w;
            }
            float tv[8] = {fmaxf(a0.x,0.f), fmaxf(a0.y,0.f), fmaxf(a0.z,0.f), fmaxf(a0.w,0.f),
                           fmaxf(a1.x,0.f), fmaxf(a1.y,0.f), fmaxf(a1.z,0.f), fmaxf(a1.w,0.f)};
            uint32_t H[4], L[4];
#pragma unroll
            for (int jp = 0; jp < 4; jp++) {
                float h0 = __bfloat162float(__float2bfloat16(tv[jp*2]));
                float h1 = __bfloat162float(__float2bfloat16(tv[jp*2+1]));
                H[jp] = pk(tv[jp*2], tv[jp*2+1]);
                L[jp] = pk(tv[jp*2] - h0, tv[jp*2+1] - h1);
            }
            uint32_t so = (uint32_t)(row * 40 + k8) * 2;
            *(uint4*)(sm + buf * ABUF + so)            = make_uint4(H[0], H[1], H[2], H[3]);
            *(uint4*)(sm + (ADEPTH + buf) * ABUF + so) = make_uint4(L[0], L[1], L[2], L[3]);
        }
    };
    auto stageB = [&](int k0, int buf) {
#pragma unroll
        for (int i = 0; i < 2; i++) {
            int idx = tid + i * 256;
            int row = idx >> 2, k8 = (idx & 3) * 8;
            uint32_t so = (uint32_t)(row * 40 + k8) * 2;
            size_t go = (size_t)(colBase + row) * KTOT + k0 + k8;
            cpa16(sb + (2 * ADEPTH + buf) * ABUF + so,     Bhi + go);
            cpa16(sb + (2 * ADEPTH + 2 + buf) * ABUF + so, Blo + go);
        }
    };

    // AMODE==1: register prefetch of A fp32 + vectorized sc/sh
    float pf[AMODE == 1 ? 16 : 1];
    const int ldRow1 = tid >> 1, ldKh1 = (tid & 1) * 16;
    auto ldgA1 = [&](int k0) {
        const float* ap = Af + (size_t)(rowBase + ldRow1) * KTOT + k0 + ldKh1;
#pragma unroll
        for (int q = 0; q < 4; q++) {
            float4 v = *(const float4*)(ap + q * 4);
            pf[q*4+0] = v.x; pf[q*4+1] = v.y; pf[q*4+2] = v.z; pf[q*4+3] = v.w;
        }
    };
    auto stsA1 = [&](int k0, int buf) {
        int kb = k0 + ldKh1;
        uint32_t H[8], L[8];
#pragma unroll
        for (int q = 0; q < 4; q++) {
            float4 sc4 = *(const float4*)&scs[kb + q * 4];
            float4 sh4 = *(const float4*)&shs[kb + q * 4];
            float t0 = fmaxf(pf[q*4+0] * sc4.x + sh4.x, 0.f);
            float t1 = fmaxf(pf[q*4+1] * sc4.y + sh4.y, 0.f);
            float t2 = fmaxf(pf[q*4+2] * sc4.z + sh4.z, 0.f);
            float t3 = fmaxf(pf[q*4+3] * sc4.w + sh4.w, 0.f);
            float h0 = __bfloat162float(__float2bfloat16(t0));
            float h1 = __bfloat162float(__float2bfloat16(t1));
            float h2 = __bfloat162float(__float2bfloat16(t2));
            float h3 = __bfloat162float(__float2bfloat16(t3));
            H[q*2]   = pk(t0, t1); H[q*2+1] = pk(t2, t3);
            L[q*2]   = pk(t0 - h0, t1 - h1);
            L[q*2+1] = pk(t2 - h2, t3 - h3);
        }
        uint32_t so = (uint32_t)(ldRow1 * 40 + ldKh1) * 2;
        *(uint4*)(sm + buf * ABUF + so)                 = make_uint4(H[0], H[1], H[2], H[3]);
        *(uint4*)(sm + buf * ABUF + so + 16)            = make_uint4(H[4], H[5], H[6], H[7]);
        *(uint4*)(sm + (ADEPTH + buf) * ABUF + so)      = make_uint4(L[0], L[1], L[2], L[3]);
        *(uint4*)(sm + (ADEPTH + buf) * ABUF + so + 16) = make_uint4(L[4], L[5], L[6], L[7]);
    };

    auto mma_chunk = [&](int abuf, int bbuf) {
#pragma unroll
        for (int kk = 0; kk < 32; kk += 16) {
            uint32_t ah[2][4], al[2][4];
#pragma unroll
            for (int mt = 0; mt < 2; mt++) {
                int ar = warp_m * 32 + mt * 16;
                uint32_t off = (uint32_t)((ar + aRowOff) * 40 + kk + aKOff) * 2;
                ldsm4(ah[mt], sb + abuf * ABUF + off);
                ldsm4(al[mt], sb + (ADEPTH + abuf) * ABUF + off);
            }
#pragma unroll
            for (int ng = 0; ng < 4; ng++) {
                int bn = warp_n * 64 + ng * 16;
                uint32_t off = (uint32_t)((bn + bRowOff) * 40 + kk + bKOff) * 2;
                uint32_t bh[4], bl[4];
                ldsm4(bh, sb + (2 * ADEPTH + bbuf) * ABUF + off);
                ldsm4(bl, sb + (2 * ADEPTH + 2 + bbuf) * ABUF + off);
#pragma unroll
                for (int hf = 0; hf < 2; hf++) {
                    int nt = ng * 2 + hf;
                    uint32_t b0 = bh[hf * 2], b1r = bh[hf * 2 + 1];
                    uint32_t c0 = bl[hf * 2], c1r = bl[hf * 2 + 1];
#pragma unroll
                    for (int mt = 0; mt < 2; mt++) {
                        mma_bf16(acc[mt][nt], ah[mt], b0, b1r);
                        mma_bf16(acc[mt][nt], ah[mt], c0, c1r);
                        mma_bf16(acc[mt][nt], al[mt], b0, b1r);
                    }
                }
            }
        }
    };

    if (AMODE == 0) {
        stageA_async(0, 0); stageB(0, 0); CPA_COMMIT();
        stageA_async(32, 1); CPA_COMMIT();
        CPA_WAIT1(); __syncthreads();
        for (int c = 0; c < C; c++) {
            if (c + 1 < C) stageB((c + 1) * 32, (c + 1) & 1);
            CPA_COMMIT();
            if (c + 2 < C) stageA_async((c + 2) * 32, (c + 2) % 3);
            CPA_COMMIT();
            mma_chunk(c % 3, c & 1);
            CPA_WAIT1(); __syncthreads();
        }
    } else {
        if (AMODE == 2) stageA_compute(0, 0);
        else          { ldgA1(0); stsA1(0, 0); }
        stageB(0, 0);
        CPA_COMMIT();
        CPA_WAIT0();
        __syncthreads();
        for (int c = 0; c < C; c++) {
            const int buf = c & 1;
            if (c + 1 < C) {
                const int k0n = (c + 1) * 32;
                if (AMODE == 2) stageA_compute(k0n, buf ^ 1);
                else            ldgA1(k0n);
                stageB(k0n, buf ^ 1);
                CPA_COMMIT();
            }
            mma_chunk(buf, buf);
            if (AMODE == 1 && c + 1 < C) stsA1((c + 1) * 32, buf ^ 1);
            CPA_WAIT0();
            __syncthreads();
        }
    }

    // ---------------- epilogue ----------------
    if (tid < 128) { pool_s[tid] = 0; redA[tid] = 0.f; redB[tid] = 0.f; }
    __syncthreads();

    if (EMODE == 0) {
#pragma unroll
        for (int mt = 0; mt < 2; mt++) {
            int r0 = rowBase + warp_m * 32 + mt * 16 + g;
            int r1 = r0 + 8;
            float m0 = (maskp[r0] != 0) ? 1.f : 0.f;
            float m1 = (maskp[r1] != 0) ? 1.f : 0.f;
#pragma unroll
            for (int nt = 0; nt < 8; nt++) {
                int lc = warp_n * 64 + nt * 8 + 2 * t4;
                int c0 = colBase + lc;
                float bx = bias_s[lc], by = bias_s[lc + 1];
                float v00 = (acc[mt][nt][0] + bx) * m0;
                float v01 = (acc[mt][nt][1] + by) * m0;
                float v10 = (acc[mt][nt][2] + bx) * m1;
                float v11 = (acc[mt][nt][3] + by) * m1;
                float h00 = __bfloat162float(__float2bfloat16(v00));
                float h01 = __bfloat162float(__float2bfloat16(v01));
                float h10 = __bfloat162float(__float2bfloat16(v10));
                float h11 = __bfloat162float(__float2bfloat16(v11));
                *(uint32_t*)&Chi[(size_t)r0 * 256 + c0] = pk(v00, v01);
                *(uint32_t*)&Chi[(size_t)r1 * 256 + c0] = pk(v10, v11);
                *(uint32_t*)&Clo[(size_t)r0 * 256 + c0] = pk(v00 - h00, v01 - h01);
                *(uint32_t*)&Clo[(size_t)r1 * 256 + c0] = pk(v10 - h10, v11 - h11);
                float p0 = fmaxf(v00, v10), p1 = fmaxf(v01, v11);
                if (p0 > 0.f) atomicMax(&pool_s[lc],     __float_as_int(p0));
                if (p1 > 0.f) atomicMax(&pool_s[lc + 1], __float_as_int(p1));
            }
        }
        __syncthreads();
        if (tid < 128) {
            int v = pool_s[tid];
            if (v > 0) atomicMax((int*)&redT[batch * 256 + colBase + tid], v);
        }
    } else if (EMODE == 1) {
#pragma unroll
        for (int nt = 0; nt < 8; nt++) {
            int lc = warp_n * 64 + nt * 8 + 2 * t4;
            int c0 = colBase + lc;
            float bx = bias_s[lc], by = bias_s[lc + 1];
            float s0 = 0.f, s1 = 0.f, q0 = 0.f, q1 = 0.f;
#pragma unroll
            for (int mt = 0; mt < 2; mt++) {
                int r0 = rowBase + warp_m * 32 + mt * 16 + g;
                int r1 = r0 + 8;
                float v00 = acc[mt][nt][0] + bx;
                float v01 = acc[mt][nt][1] + by;
                float v10 = acc[mt][nt][2] + bx;
                float v11 = acc[mt][nt][3] + by;
                *(float2*)&Cf[(size_t)r0 * 256 + c0] = make_float2(v00, v01);
                *(float2*)&Cf[(size_t)r1 * 256 + c0] = make_float2(v10, v11);
                if (maskp[r0]) { s0 += v00; s1 += v01; q0 += v00*v00; q1 += v01*v01; }
                if (maskp[r1]) { s0 += v10; s1 += v11; q0 += v10*v10; q1 += v11*v11; }
            }
            atomicAdd(&redA[lc],     s0);
            atomicAdd(&redA[lc + 1], s1);
            atomicAdd(&redB[lc],     q0);
            atomicAdd(&redB[lc + 1], q1);
        }
        __syncthreads();
        if (tid < 128) {
            atomicAdd(&g_sum2[colBase + tid], redA[tid]);
            atomicAdd(&g_ss2[colBase + tid],  redB[tid]);
        }
    } else {
#pragma unroll
        for (int nt = 0; nt < 8; nt++) {
            int lc = warp_n * 64 + nt * 8 + 2 * t4;
            float bx = bias_s[lc], by = bias_s[lc + 1];
            float p0 = 0.f, p1 = 0.f;
#pragma unroll
            for (int mt = 0; mt < 2; mt++) {
                int r0 = rowBase + warp_m * 32 + mt * 16 + g;
                int r1 = r0 + 8;
                float m0 = (maskp[r0] != 0) ? 1.f : 0.f;
                float m1 = (maskp[r1] != 0) ? 1.f : 0.f;
                p0 = fmaxf(p0, (acc[mt][nt][0] + bx) * m0);
                p1 = fmaxf(p1, (acc[mt][nt][1] + by) * m0);
                p0 = fmaxf(p0, (acc[mt][nt][2] + bx) * m1);
                p1 = fmaxf(p1, (acc[mt][nt][3] + by) * m1);
            }
            if (p0 > 0.f) atomicMax(&pool_s[lc],     __float_as_int(p0));
            if (p1 > 0.f) atomicMax(&pool_s[lc + 1], __float_as_int(p1));
        }
        __syncthreads();
        if (tid < 128) {
            int v = pool_s[tid];
            if (v > 0) atomicMax((int*)&redT[batch * 128 + tid], v);
        }
    }
}

// ---------------- launch ----------------
extern "C" void kernel_launch(void* const* d_in, const int* in_sizes, int n_in,
                              void* d_out, int out_size) {
    const float* x   = (const float*)d_in[0];
    const int*   mask= (const int*)  d_in[1];
    const float* W1  = (const float*)d_in[2];
    const float* b1  = (const float*)d_in[3];
    const float* g1  = (const float*)d_in[4];
    const float* be1 = (const float*)d_in[5];
    const float* W2  = (const float*)d_in[6];
    const float* b2  = (const float*)d_in[7];
    const float* W3  = (const float*)d_in[8];
    const float* b3  = (const float*)d_in[9];
    const float* g2  = (const float*)d_in[10];
    const float* be2 = (const float*)d_in[11];
    const float* W4  = (const float*)d_in[12];
    const float* b4  = (const float*)d_in[13];
    float* out = (float*)d_out;

    float *p_h2, *p_pooled, *p_pb, *p_sc1, *p_sh1, *p_sc2, *p_sh2;
    __nv_bfloat16 *p_yhi, *p_ylo, *p_w2hi, *p_w2lo, *p_w3hi, *p_w3lo, *p_w4hi, *p_w4lo;
    cudaGetSymbolAddress((void**)&p_h2,     g_h2);
    cudaGetSymbolAddress((void**)&p_pooled, g_pooled);
    cudaGetSymbolAddress((void**)&p_pb,     g_pb);
    cudaGetSymbolAddress((void**)&p_sc1,    g_scale1);
    cudaGetSymbolAddress((void**)&p_sh1,    g_shift1);
    cudaGetSymbolAddress((void**)&p_sc2,    g_scale2);
    cudaGetSymbolAddress((void**)&p_sh2,    g_shift2);
    cudaGetSymbolAddress((void**)&p_yhi,    g_yhi);
    cudaGetSymbolAddress((void**)&p_ylo,    g_ylo);
    cudaGetSymbolAddress((void**)&p_w2hi,   g_w2hi);
    cudaGetSymbolAddress((void**)&p_w2lo,   g_w2lo);
    cudaGetSymbolAddress((void**)&p_w3hi,   g_w3hi);
    cudaGetSymbolAddress((void**)&p_w3lo,   g_w3lo);
    cudaGetSymbolAddress((void**)&p_w4hi,   g_w4hi);
    cudaGetSymbolAddress((void**)&p_w4lo,   g_w4lo);

    const int FBYTES = (128*3 + 256*2 + 768 + 128) * 4;
    const int SM_G2 = 8  * ABUF + FBYTES;
    const int SM_G3 = 10 * ABUF + FBYTES;
    const int SM_G4 = 8  * ABUF + FBYTES;
    cudaFuncSetAttribute(k_tc<128,2,0>, cudaFuncAttributeMaxDynamicSharedMemorySize, SM_G2);
    cudaFuncSetAttribute(k_tc<256,0,1>, cudaFuncAttributeMaxDynamicSharedMemorySize, SM_G3);
    cudaFuncSetAttribute(k_tc<256,1,2>, cudaFuncAttributeMaxDynamicSharedMemorySize, SM_G4);

    k_prep   <<<512, 256>>>(out, p_pooled, W2, W3, W4);
    k_h_stats<<<2048, 128>>>(x, mask, W1, b1);
    k_fin1   <<<1, 128>>>(g1, be1);

    // GEMM2: y = (relu(bn1(x@W1+b1)) @ W2 + b2)*mask [+ max-pool]
    k_tc<128,2,0><<<dim3(2, 2048), 256, SM_G2>>>(nullptr, x, nullptr, nullptr, p_w2hi, p_w2lo,
        b2, mask, p_sc1, p_sh1, W1, b1, nullptr, p_yhi, p_ylo, p_pooled);
    k_pb     <<<512, 256>>>(W3, b3);
    // GEMM3: h2 = y @ W3[:256] + pb[batch]  [+ fused BN2 stats]
    k_tc<256,0,1><<<dim3(2, 2048), 256, SM_G3>>>(nullptr, nullptr, p_yhi, p_ylo, p_w3hi, p_w3lo,
        p_pb, mask, nullptr, nullptr, nullptr, nullptr, p_h2, nullptr, nullptr, nullptr);
    k_fin2   <<<1, 256>>>(g2, be2);
    // GEMM4: out = max_n ((relu(bn2(h2)) @ W4 + b4)*mask)
    k_tc<256,1,2><<<dim3(1, 2048), 256, SM_G4>>>(p_h2, nullptr, nullptr, nullptr, p_w4hi, p_w4lo,
        b4, mask, p_sc2, p_sh2, nullptr, nullptr, nullptr, nullptr, nullptr, out);
}